// round 5
// baseline (speedup 1.0000x reference)
#include <cuda_runtime.h>

// GINE-conv network:
//   h = emb[x]; h = leaky_relu(gine(h, E1)); h2 = gine(h, E2); out = h2 @ h2.T
// N=8192, E=262144, dims 128 -> 64 -> 32, out 8192x8192 f32.
// R5: CSR (dst-sorted) edge aggregation in registers -- NO float atomics.
//     Gemm reverted to R2-exact scalar version (f32x2 experiment regressed).

#define NN     8192
#define NE     262144
#define EMB    128
#define D1     64
#define D2     32
#define EPSF   1e-9f
#define SLOPEF 0.01f

__device__ __align__(16) float g_h[NN * EMB];
__device__ __align__(16) float g_agg1[NN * EMB];   // t1 = (1+eps)h + sum
__device__ __align__(16) float g_h1[NN * D1];
__device__ __align__(16) float g_agg2[NN * D1];    // t2 = (1+eps)h1 + sum
__device__ __align__(16) float g_h2[NN * D2];
__device__ int g_x[NN];
__device__ int g_src[NE];
__device__ int g_dst[NE];
__device__ int g_cnt[NN];          // counts, then reused as scatter cursor
__device__ int g_rowstart[NN + 1];
__device__ int g_eidx[NE];         // edge ids grouped by dst

__device__ __forceinline__ void fma4(float4& a, float s, const float4& w) {
    a.x = fmaf(s, w.x, a.x);
    a.y = fmaf(s, w.y, a.y);
    a.z = fmaf(s, w.z, a.z);
    a.w = fmaf(s, w.w, a.w);
}
__device__ __forceinline__ void fma2s(float2& a, float s, const float2& w) {
    a.x = fmaf(s, w.x, a.x);
    a.y = fmaf(s, w.y, a.y);
}

// ---------------------------------------------------------------------------
// K0: normalize index dtypes (int64 vs int32 delivery) + zero counters.
// ---------------------------------------------------------------------------
__global__ void k_convert(const unsigned* __restrict__ xbuf,
                          const unsigned* __restrict__ eibuf) {
    unsigned odd_or = 0;
#pragma unroll
    for (int i = 0; i < 32; i++) odd_or |= eibuf[2 * i + 1];
    bool mode64 = (odd_or == 0);

    int t = blockIdx.x * blockDim.x + threadIdx.x;
    if (t < NE) {
        g_src[t] = (int)(mode64 ? eibuf[2 * t]        : eibuf[t]);
        g_dst[t] = (int)(mode64 ? eibuf[2 * (NE + t)] : eibuf[NE + t]);
    }
    if (t < NN) {
        g_x[t] = (int)(mode64 ? xbuf[2 * t] : xbuf[t]);
        g_cnt[t] = 0;
    }
}

// ---------------------------------------------------------------------------
// CSR build: count -> scan -> scatter
// ---------------------------------------------------------------------------
__global__ void k_count() {
    int t = blockIdx.x * blockDim.x + threadIdx.x;
    if (t < NE) atomicAdd(&g_cnt[g_dst[t]], 1);
}

__global__ void __launch_bounds__(1024) k_scan() {
    __shared__ int wsum[32];
    int tid  = threadIdx.x;           // 0..1023
    int base = tid * 8;               // 1024*8 = 8192
    int v[8], loc = 0;
#pragma unroll
    for (int i = 0; i < 8; i++) { v[i] = g_cnt[base + i]; loc += v[i]; }

    int lane = tid & 31, wid = tid >> 5;
    int x = loc;
#pragma unroll
    for (int o = 1; o < 32; o <<= 1) {
        int y = __shfl_up_sync(0xffffffffu, x, o);
        if (lane >= o) x += y;
    }
    if (lane == 31) wsum[wid] = x;
    __syncthreads();
    if (wid == 0) {
        int y = wsum[lane];
#pragma unroll
        for (int o = 1; o < 32; o <<= 1) {
            int z = __shfl_up_sync(0xffffffffu, y, o);
            if (lane >= o) y += z;
        }
        wsum[lane] = y;
    }
    __syncthreads();
    int excl = x - loc + (wid > 0 ? wsum[wid - 1] : 0);
    int run = excl;
#pragma unroll
    for (int i = 0; i < 8; i++) {
        g_rowstart[base + i] = run;
        run += v[i];
        g_cnt[base + i] = 0;          // reset for scatter cursor
    }
    if (tid == 1023) g_rowstart[NN] = run;   // = NE
}

__global__ void k_scatter() {
    int t = blockIdx.x * blockDim.x + threadIdx.x;
    if (t < NE) {
        int d = g_dst[t];
        int p = atomicAdd(&g_cnt[d], 1);
        g_eidx[g_rowstart[d] + p] = t;
    }
}

// ---------------------------------------------------------------------------
// K1: h = emb[x]
// ---------------------------------------------------------------------------
__global__ void k_embed(const float4* __restrict__ emb4) {
    int t = blockIdx.x * blockDim.x + threadIdx.x;
    int node = t >> 5;
    int c    = t & 31;
    ((float4*)g_h)[t] = emb4[g_x[node] * 32 + c];
}

// ---------------------------------------------------------------------------
// K2: edge pass 1, CSR. Warp per node; lane owns 4 of 128 cols.
// t1[n] = (1+eps)h[n] + sum_{e: dst=n} relu(h[src] + ea[e]@E1w + E1b)
// ---------------------------------------------------------------------------
__global__ void __launch_bounds__(256)
k_edge1(const float4* __restrict__ ea4,
        const float4* __restrict__ w4,     // E1w as (16 x 32) float4
        const float4* __restrict__ b4) {   // E1b as 32 float4
    int lane = threadIdx.x & 31;
    int node = (blockIdx.x * blockDim.x + threadIdx.x) >> 5;

    float4 w[16];
#pragma unroll
    for (int k = 0; k < 16; k++) w[k] = w4[k * 32 + lane];
    float4 bias = b4[lane];

    const float4* h4 = (const float4*)g_h;

    int i    = g_rowstart[node];
    int iend = g_rowstart[node + 1];

    float4 sum = make_float4(0.f, 0.f, 0.f, 0.f);
    for (; i < iend; i++) {
        int e   = g_eidx[i];
        int src = g_src[e];
        float4 ea0 = ea4[e * 4 + 0];
        float4 ea1 = ea4[e * 4 + 1];
        float4 ea2 = ea4[e * 4 + 2];
        float4 ea3 = ea4[e * 4 + 3];

        float4 acc = bias;
        fma4(acc, ea0.x, w[0]);  fma4(acc, ea0.y, w[1]);
        fma4(acc, ea0.z, w[2]);  fma4(acc, ea0.w, w[3]);
        fma4(acc, ea1.x, w[4]);  fma4(acc, ea1.y, w[5]);
        fma4(acc, ea1.z, w[6]);  fma4(acc, ea1.w, w[7]);
        fma4(acc, ea2.x, w[8]);  fma4(acc, ea2.y, w[9]);
        fma4(acc, ea2.z, w[10]); fma4(acc, ea2.w, w[11]);
        fma4(acc, ea3.x, w[12]); fma4(acc, ea3.y, w[13]);
        fma4(acc, ea3.z, w[14]); fma4(acc, ea3.w, w[15]);

        float4 hv = h4[src * 32 + lane];
        sum.x += fmaxf(hv.x + acc.x, 0.f);
        sum.y += fmaxf(hv.y + acc.y, 0.f);
        sum.z += fmaxf(hv.z + acc.z, 0.f);
        sum.w += fmaxf(hv.w + acc.w, 0.f);
    }

    float4 hn = h4[node * 32 + lane];
    float4 out;
    out.x = fmaf(1.f + EPSF, hn.x, sum.x);
    out.y = fmaf(1.f + EPSF, hn.y, sum.y);
    out.z = fmaf(1.f + EPSF, hn.z, sum.z);
    out.w = fmaf(1.f + EPSF, hn.w, sum.w);
    ((float4*)g_agg1)[node * 32 + lane] = out;
}

// ---------------------------------------------------------------------------
// K3: h1 = leaky_relu(t1 @ W1 + b1).  Warp per node; lane owns 2 cols.
// ---------------------------------------------------------------------------
__global__ void __launch_bounds__(256)
k_lin1(const float* __restrict__ W1, const float* __restrict__ b1) {
    __shared__ float2 sW[EMB][D1 / 2];     // 32 KB, [k][c2]
    __shared__ float  srow[8][EMB + 4];

    int tid  = threadIdx.x;
    int warp = tid >> 5;
    int lane = tid & 31;

    for (int i = tid; i < EMB * (D1 / 2); i += 256)
        sW[i >> 5][i & 31] = ((const float2*)W1)[i];

    int n = blockIdx.x * 8 + warp;
    float4 v = *(const float4*)(g_agg1 + (size_t)n * EMB + lane * 4);
    *(float4*)&srow[warp][lane * 4] = v;
    __syncthreads();

    float2 acc = ((const float2*)b1)[lane];
#pragma unroll
    for (int k = 0; k < EMB; k++) {
        float r = srow[warp][k];
        float2 w = sW[k][lane];
        acc.x = fmaf(r, w.x, acc.x);
        acc.y = fmaf(r, w.y, acc.y);
    }

    float a0 = acc.x >= 0.f ? acc.x : SLOPEF * acc.x;
    float a1 = acc.y >= 0.f ? acc.y : SLOPEF * acc.y;
    ((float2*)(g_h1 + (size_t)n * D1))[lane] = make_float2(a0, a1);
}

// ---------------------------------------------------------------------------
// K4: edge pass 2, CSR. Warp per node; lane owns 2 of 64 cols.
// t2[n] = (1+eps)h1[n] + sum relu(h1[src] + ea[e]@E2w + E2b)
// ---------------------------------------------------------------------------
__global__ void __launch_bounds__(256)
k_edge2(const float4* __restrict__ ea4,
        const float2* __restrict__ w2v,    // E2w as (16 x 32) float2
        const float2* __restrict__ b2v) {  // E2b as 32 float2
    int lane = threadIdx.x & 31;
    int node = (blockIdx.x * blockDim.x + threadIdx.x) >> 5;

    float2 w[16];
#pragma unroll
    for (int k = 0; k < 16; k++) w[k] = w2v[k * 32 + lane];
    float2 bias = b2v[lane];

    const float2* h2v = (const float2*)g_h1;

    int i    = g_rowstart[node];
    int iend = g_rowstart[node + 1];

    float2 sum = make_float2(0.f, 0.f);
    for (; i < iend; i++) {
        int e   = g_eidx[i];
        int src = g_src[e];
        float4 ea0 = ea4[e * 4 + 0];
        float4 ea1 = ea4[e * 4 + 1];
        float4 ea2 = ea4[e * 4 + 2];
        float4 ea3 = ea4[e * 4 + 3];

        float2 acc = bias;
        fma2s(acc, ea0.x, w[0]);  fma2s(acc, ea0.y, w[1]);
        fma2s(acc, ea0.z, w[2]);  fma2s(acc, ea0.w, w[3]);
        fma2s(acc, ea1.x, w[4]);  fma2s(acc, ea1.y, w[5]);
        fma2s(acc, ea1.z, w[6]);  fma2s(acc, ea1.w, w[7]);
        fma2s(acc, ea2.x, w[8]);  fma2s(acc, ea2.y, w[9]);
        fma2s(acc, ea2.z, w[10]); fma2s(acc, ea2.w, w[11]);
        fma2s(acc, ea3.x, w[12]); fma2s(acc, ea3.y, w[13]);
        fma2s(acc, ea3.z, w[14]); fma2s(acc, ea3.w, w[15]);

        float2 hv = h2v[src * 32 + lane];
        sum.x += fmaxf(hv.x + acc.x, 0.f);
        sum.y += fmaxf(hv.y + acc.y, 0.f);
    }

    float2 hn = h2v[node * 32 + lane];
    float2 out;
    out.x = fmaf(1.f + EPSF, hn.x, sum.x);
    out.y = fmaf(1.f + EPSF, hn.y, sum.y);
    ((float2*)g_agg2)[node * 32 + lane] = out;
}

// ---------------------------------------------------------------------------
// K5: h2 = t2 @ W2 + b2.  Warp per node; lane owns 1 col.
// ---------------------------------------------------------------------------
__global__ void __launch_bounds__(256)
k_lin2(const float* __restrict__ W2, const float* __restrict__ b2) {
    __shared__ float sW[D1][D2 + 1];
    __shared__ float srow[8][D1 + 4];

    int tid  = threadIdx.x;
    int warp = tid >> 5;
    int lane = tid & 31;

    for (int i = tid; i < D1 * D2; i += 256)
        sW[i >> 5][i & 31] = W2[i];

    int n = blockIdx.x * 8 + warp;
    float2 rv = *(const float2*)(g_agg2 + (size_t)n * D1 + lane * 2);
    srow[warp][lane * 2]     = rv.x;
    srow[warp][lane * 2 + 1] = rv.y;
    __syncthreads();

    float acc = b2[lane];
#pragma unroll
    for (int k = 0; k < D1; k++)
        acc = fmaf(srow[warp][k], sW[k][lane], acc);

    g_h2[(size_t)n * D2 + lane] = acc;
}

// ---------------------------------------------------------------------------
// K6: C = h2 @ h2^T (R2-exact scalar version). Symmetric: upper-tri tiles,
// mirrored writes. 128x128 tile, 256 threads, 8x8 micro-tile per thread.
// ---------------------------------------------------------------------------
#define GP 129  // smem row pad (odd stride -> conflict-free transposed access)

__global__ void __launch_bounds__(256)
k_gemm(float* __restrict__ C) {
    int bi = blockIdx.y;
    int bj = blockIdx.x;
    if (bj < bi) return;

    __shared__ float As[D2][GP];   // [k][row]
    __shared__ float Bs[D2][GP];

    int tid = threadIdx.x;
    for (int i = tid; i < 128 * D2; i += 256) {
        int r = i >> 5;
        int k = i & 31;
        As[k][r] = g_h2[(size_t)(bi * 128 + r) * D2 + k];
        Bs[k][r] = g_h2[(size_t)(bj * 128 + r) * D2 + k];
    }
    __syncthreads();

    int tx = tid & 15;
    int ty = tid >> 4;
    int i0 = ty * 8;
    int j0 = tx * 8;

    float acc[8][8];
#pragma unroll
    for (int ii = 0; ii < 8; ii++)
#pragma unroll
        for (int jj = 0; jj < 8; jj++) acc[ii][jj] = 0.f;

#pragma unroll 4
    for (int k = 0; k < D2; k++) {
        float a[8], b[8];
#pragma unroll
        for (int ii = 0; ii < 8; ii++) a[ii] = As[k][i0 + ii];
#pragma unroll
        for (int jj = 0; jj < 8; jj++) b[jj] = Bs[k][j0 + jj];
#pragma unroll
        for (int ii = 0; ii < 8; ii++)
#pragma unroll
            for (int jj = 0; jj < 8; jj++)
                acc[ii][jj] = fmaf(a[ii], b[jj], acc[ii][jj]);
    }

    {
        float* Cp = C + (size_t)(bi * 128 + i0) * NN + bj * 128 + j0;
#pragma unroll
        for (int ii = 0; ii < 8; ii++) {
            float4 v0 = make_float4(acc[ii][0], acc[ii][1], acc[ii][2], acc[ii][3]);
            float4 v1 = make_float4(acc[ii][4], acc[ii][5], acc[ii][6], acc[ii][7]);
            ((float4*)(Cp + (size_t)ii * NN))[0] = v0;
            ((float4*)(Cp + (size_t)ii * NN))[1] = v1;
        }
    }
    if (bi != bj) {
        float* Cp = C + (size_t)(bj * 128 + j0) * NN + bi * 128 + i0;
#pragma unroll
        for (int jj = 0; jj < 8; jj++) {
            float4 v0 = make_float4(acc[0][jj], acc[1][jj], acc[2][jj], acc[3][jj]);
            float4 v1 = make_float4(acc[4][jj], acc[5][jj], acc[6][jj], acc[7][jj]);
            ((float4*)(Cp + (size_t)jj * NN))[0] = v0;
            ((float4*)(Cp + (size_t)jj * NN))[1] = v1;
        }
    }
}

// ---------------------------------------------------------------------------
extern "C" void kernel_launch(void* const* d_in, const int* in_sizes, int n_in,
                              void* d_out, int out_size) {
    const unsigned* xbuf  = (const unsigned*)d_in[0];
    const unsigned* eibuf = (const unsigned*)d_in[1];
    const float*    ea    = (const float*)d_in[2];
    const float*    emb   = (const float*)d_in[3];
    const float*    W1    = (const float*)d_in[4];
    const float*    b1    = (const float*)d_in[5];
    const float*    E1w   = (const float*)d_in[6];
    const float*    E1b   = (const float*)d_in[7];
    const float*    W2    = (const float*)d_in[8];
    const float*    b2    = (const float*)d_in[9];
    const float*    E2w   = (const float*)d_in[10];
    const float*    E2b   = (const float*)d_in[11];
    float* out = (float*)d_out;

    k_convert<<<(NE + 255) / 256, 256>>>(xbuf, eibuf);
    k_count<<<(NE + 255) / 256, 256>>>();
    k_scan<<<1, 1024>>>();
    k_scatter<<<(NE + 255) / 256, 256>>>();
    k_embed<<<NN * 32 / 256, 256>>>((const float4*)emb);
    k_edge1<<<NN / 8, 256>>>((const float4*)ea,
                             (const float4*)E1w, (const float4*)E1b);
    k_lin1<<<NN / 8, 256>>>(W1, b1);
    k_edge2<<<NN / 8, 256>>>((const float4*)ea,
                             (const float2*)E2w, (const float2*)E2b);
    k_lin2<<<NN / 8, 256>>>(W2, b2);
    dim3 g(NN / 128, NN / 128);
    k_gemm<<<g, 256>>>(out);
}

// round 6
// speedup vs baseline: 1.1822x; 1.1822x over previous
#include <cuda_runtime.h>
#include <cuda_bf16.h>

// GINE-conv network:
//   h = emb[x]; h = leaky_relu(gine(h, E1)); h2 = gine(h, E2); out = h2 @ h2.T
// N=8192, E=262144, dims 128 -> 64 -> 32, out 8192x8192 f32.
// R6: R2-validated atomic edge pipeline + tensor-core (bf16 hi/lo split) gemm.

#define NN     8192
#define NE     262144
#define EMB    128
#define D1     64
#define D2     32
#define EPSF   1e-9f
#define SLOPEF 0.01f

__device__ __align__(16) float g_h[NN * EMB];
__device__ __align__(16) float g_agg1[NN * EMB];
__device__ __align__(16) float g_h1[NN * D1];
__device__ __align__(16) float g_agg2[NN * D1];
__device__ __align__(16) unsigned short g_h2hi[NN * D2];   // bf16 hi
__device__ __align__(16) unsigned short g_h2lo[NN * D2];   // bf16 lo residual
__device__ int g_x[NN];
__device__ int g_src[NE];
__device__ int g_dst[NE];

__device__ __forceinline__ void fma4(float4& a, float s, const float4& w) {
    a.x = fmaf(s, w.x, a.x);
    a.y = fmaf(s, w.y, a.y);
    a.z = fmaf(s, w.z, a.z);
    a.w = fmaf(s, w.w, a.w);
}
__device__ __forceinline__ void fma2s(float2& a, float s, const float2& w) {
    a.x = fmaf(s, w.x, a.x);
    a.y = fmaf(s, w.y, a.y);
}

// ---------------------------------------------------------------------------
// K0: normalize index dtypes (int64 vs int32 delivery; detection as before).
// ---------------------------------------------------------------------------
__global__ void k_convert(const unsigned* __restrict__ xbuf,
                          const unsigned* __restrict__ eibuf) {
    unsigned odd_or = 0;
#pragma unroll
    for (int i = 0; i < 32; i++) odd_or |= eibuf[2 * i + 1];
    bool mode64 = (odd_or == 0);

    int t = blockIdx.x * blockDim.x + threadIdx.x;
    if (t < NE) {
        g_src[t] = (int)(mode64 ? eibuf[2 * t]        : eibuf[t]);
        g_dst[t] = (int)(mode64 ? eibuf[2 * (NE + t)] : eibuf[NE + t]);
    }
    if (t < NN) g_x[t] = (int)(mode64 ? xbuf[2 * t] : xbuf[t]);
}

// ---------------------------------------------------------------------------
// K1: h = emb[x];  agg1 = (1+eps)*h
// ---------------------------------------------------------------------------
__global__ void k_embed(const float4* __restrict__ emb4) {
    int t = blockIdx.x * blockDim.x + threadIdx.x;
    int node = t >> 5;
    int c    = t & 31;
    float4 v = emb4[g_x[node] * 32 + c];
    ((float4*)g_h)[t] = v;
    float4 a = make_float4(v.x * (1.f + EPSF), v.y * (1.f + EPSF),
                           v.z * (1.f + EPSF), v.w * (1.f + EPSF));
    ((float4*)g_agg1)[t] = a;
}

// ---------------------------------------------------------------------------
// K2: edge pass 1 (R2-validated). Warp per edge; lane owns 4 cols.
// ---------------------------------------------------------------------------
__global__ void __launch_bounds__(256)
k_edge1(const float4* __restrict__ ea4,
        const float4* __restrict__ w4,     // E1w as (16 x 32) float4
        const float4* __restrict__ b4) {   // E1b as 32 float4
    int lane = threadIdx.x & 31;
    int warp = (blockIdx.x * blockDim.x + threadIdx.x) >> 5;
    int nw   = (gridDim.x * blockDim.x) >> 5;

    float4 w[16];
#pragma unroll
    for (int k = 0; k < 16; k++) w[k] = w4[k * 32 + lane];
    float4 bias = b4[lane];

    const float4* h4 = (const float4*)g_h;

    for (int e = warp; e < NE; e += nw) {
        int src = g_src[e];
        int dst = g_dst[e];
        float4 ea0 = ea4[e * 4 + 0];
        float4 ea1 = ea4[e * 4 + 1];
        float4 ea2 = ea4[e * 4 + 2];
        float4 ea3 = ea4[e * 4 + 3];

        float4 acc = bias;
        fma4(acc, ea0.x, w[0]);  fma4(acc, ea0.y, w[1]);
        fma4(acc, ea0.z, w[2]);  fma4(acc, ea0.w, w[3]);
        fma4(acc, ea1.x, w[4]);  fma4(acc, ea1.y, w[5]);
        fma4(acc, ea1.z, w[6]);  fma4(acc, ea1.w, w[7]);
        fma4(acc, ea2.x, w[8]);  fma4(acc, ea2.y, w[9]);
        fma4(acc, ea2.z, w[10]); fma4(acc, ea2.w, w[11]);
        fma4(acc, ea3.x, w[12]); fma4(acc, ea3.y, w[13]);
        fma4(acc, ea3.z, w[14]); fma4(acc, ea3.w, w[15]);

        float4 hv = h4[src * 32 + lane];
        float m0 = fmaxf(hv.x + acc.x, 0.f);
        float m1 = fmaxf(hv.y + acc.y, 0.f);
        float m2 = fmaxf(hv.z + acc.z, 0.f);
        float m3 = fmaxf(hv.w + acc.w, 0.f);

        float* p = g_agg1 + (size_t)dst * EMB + lane * 4;
        asm volatile("red.global.add.v4.f32 [%0], {%1,%2,%3,%4};"
                     :: "l"(p), "f"(m0), "f"(m1), "f"(m2), "f"(m3)
                     : "memory");
    }
}

// ---------------------------------------------------------------------------
// K3: h1 = leaky_relu(agg1 @ W1 + b1);  agg2 = (1+eps)*h1  (R2 version)
// ---------------------------------------------------------------------------
__global__ void __launch_bounds__(256)
k_lin1(const float* __restrict__ W1, const float* __restrict__ b1) {
    __shared__ float sW[EMB * D1];     // 32 KB
    __shared__ float srow[4 * EMB];    // 2 KB
    int tid = threadIdx.x;
    for (int i = tid; i < EMB * D1; i += 256) sW[i] = W1[i];
    int node0 = blockIdx.x * 4;
    for (int i = tid; i < 4 * EMB; i += 256) srow[i] = g_agg1[node0 * EMB + i];
    __syncthreads();

    int ln = tid >> 6;     // 0..3
    int c  = tid & 63;
    const float* row = &srow[ln * EMB];
    float acc = b1[c];
#pragma unroll 8
    for (int k = 0; k < EMB; k++) acc = fmaf(row[k], sW[k * D1 + c], acc);
    float v = acc >= 0.f ? acc : SLOPEF * acc;
    int n = node0 + ln;
    g_h1[n * D1 + c]   = v;
    g_agg2[n * D1 + c] = (1.f + EPSF) * v;
}

// ---------------------------------------------------------------------------
// K4: edge pass 2 (R2-validated). Warp per edge; lane owns 2 cols.
// ---------------------------------------------------------------------------
__global__ void __launch_bounds__(256)
k_edge2(const float4* __restrict__ ea4,
        const float2* __restrict__ w2v,    // E2w as (16 x 32) float2
        const float2* __restrict__ b2v) {  // E2b as 32 float2
    int lane = threadIdx.x & 31;
    int warp = (blockIdx.x * blockDim.x + threadIdx.x) >> 5;
    int nw   = (gridDim.x * blockDim.x) >> 5;

    float2 w[16];
#pragma unroll
    for (int k = 0; k < 16; k++) w[k] = w2v[k * 32 + lane];
    float2 bias = b2v[lane];

    const float2* h2v = (const float2*)g_h1;

    for (int e = warp; e < NE; e += nw) {
        int src = g_src[e];
        int dst = g_dst[e];
        float4 ea0 = ea4[e * 4 + 0];
        float4 ea1 = ea4[e * 4 + 1];
        float4 ea2 = ea4[e * 4 + 2];
        float4 ea3 = ea4[e * 4 + 3];

        float2 acc = bias;
        fma2s(acc, ea0.x, w[0]);  fma2s(acc, ea0.y, w[1]);
        fma2s(acc, ea0.z, w[2]);  fma2s(acc, ea0.w, w[3]);
        fma2s(acc, ea1.x, w[4]);  fma2s(acc, ea1.y, w[5]);
        fma2s(acc, ea1.z, w[6]);  fma2s(acc, ea1.w, w[7]);
        fma2s(acc, ea2.x, w[8]);  fma2s(acc, ea2.y, w[9]);
        fma2s(acc, ea2.z, w[10]); fma2s(acc, ea2.w, w[11]);
        fma2s(acc, ea3.x, w[12]); fma2s(acc, ea3.y, w[13]);
        fma2s(acc, ea3.z, w[14]); fma2s(acc, ea3.w, w[15]);

        float2 hv = h2v[src * 32 + lane];
        float m0 = fmaxf(hv.x + acc.x, 0.f);
        float m1 = fmaxf(hv.y + acc.y, 0.f);

        float* p = g_agg2 + (size_t)dst * D1 + lane * 2;
        asm volatile("red.global.add.v2.f32 [%0], {%1,%2};"
                     :: "l"(p), "f"(m0), "f"(m1)
                     : "memory");
    }
}

// ---------------------------------------------------------------------------
// K5: h2 = agg2 @ W2 + b2, stored as bf16 hi + bf16 lo residual.
// Warp per node; lane owns 1 col.
// ---------------------------------------------------------------------------
__global__ void __launch_bounds__(256)
k_lin2(const float* __restrict__ W2, const float* __restrict__ b2) {
    __shared__ float sW[D1][D2 + 1];
    __shared__ float srow[8][D1 + 4];

    int tid  = threadIdx.x;
    int warp = tid >> 5;
    int lane = tid & 31;

    for (int i = tid; i < D1 * D2; i += 256)
        sW[i >> 5][i & 31] = W2[i];

    int n = blockIdx.x * 8 + warp;
    float2 rv = *(const float2*)(g_agg2 + (size_t)n * D1 + lane * 2);
    srow[warp][lane * 2]     = rv.x;
    srow[warp][lane * 2 + 1] = rv.y;
    __syncthreads();

    float acc = b2[lane];
#pragma unroll
    for (int k = 0; k < D1; k++)
        acc = fmaf(srow[warp][k], sW[k][lane], acc);

    __nv_bfloat16 hi = __float2bfloat16_rn(acc);
    float res = acc - __bfloat162float(hi);
    __nv_bfloat16 lo = __float2bfloat16_rn(res);
    g_h2hi[(size_t)n * D2 + lane] = *(unsigned short*)&hi;
    g_h2lo[(size_t)n * D2 + lane] = *(unsigned short*)&lo;
}

// ---------------------------------------------------------------------------
// K6: C = h2 @ h2^T via bf16 tensor cores with hi/lo split:
//   C = hi@hi^T + hi@lo^T + lo@hi^T   (lo@lo^T ~ 2^-16 rel, dropped)
// 128x128 tile per block, 8 warps (4x2), warp = 32x64, mma.m16n8k16.
// Smem rows stride 40 bf16 (80B): ldmatrix rows hit distinct banks.
// ---------------------------------------------------------------------------
#define SROW 40

__device__ __forceinline__ void ldx4(unsigned r[4], unsigned addr) {
    asm volatile("ldmatrix.sync.aligned.m8n8.x4.shared.b16 {%0,%1,%2,%3}, [%4];"
                 : "=r"(r[0]), "=r"(r[1]), "=r"(r[2]), "=r"(r[3]) : "r"(addr));
}
__device__ __forceinline__ void mma16816(float c[4], const unsigned a[4],
                                         unsigned b0, unsigned b1) {
    asm volatile(
        "mma.sync.aligned.m16n8k16.row.col.f32.bf16.bf16.f32 "
        "{%0,%1,%2,%3}, {%4,%5,%6,%7}, {%8,%9}, {%0,%1,%2,%3};"
        : "+f"(c[0]), "+f"(c[1]), "+f"(c[2]), "+f"(c[3])
        : "r"(a[0]), "r"(a[1]), "r"(a[2]), "r"(a[3]), "r"(b0), "r"(b1));
}

__global__ void __launch_bounds__(256)
k_gemm(float* __restrict__ C) {
    __shared__ __align__(16) unsigned short Ah[128 * SROW];
    __shared__ __align__(16) unsigned short Al[128 * SROW];
    __shared__ __align__(16) unsigned short Bh[128 * SROW];
    __shared__ __align__(16) unsigned short Bl[128 * SROW];

    int bi = blockIdx.y;
    int bj = blockIdx.x;
    int tid = threadIdx.x;

    const unsigned* h2h = (const unsigned*)g_h2hi;
    const unsigned* h2l = (const unsigned*)g_h2lo;
    unsigned* Ah32 = (unsigned*)Ah;
    unsigned* Al32 = (unsigned*)Al;
    unsigned* Bh32 = (unsigned*)Bh;
    unsigned* Bl32 = (unsigned*)Bl;

    // Stage tiles: 128 rows x 16 u32 (32 bf16) each.
    for (int idx = tid; idx < 128 * 16; idx += 256) {
        int r  = idx >> 4;
        int c2 = idx & 15;
        int sm = r * (SROW / 2) + c2;
        Ah32[sm] = h2h[(size_t)(bi * 128 + r) * 16 + c2];
        Al32[sm] = h2l[(size_t)(bi * 128 + r) * 16 + c2];
        Bh32[sm] = h2h[(size_t)(bj * 128 + r) * 16 + c2];
        Bl32[sm] = h2l[(size_t)(bj * 128 + r) * 16 + c2];
    }
    __syncthreads();

    int w    = tid >> 5;
    int lane = tid & 31;
    int wm   = (w >> 1) * 32;    // 4 row groups
    int wn   = (w & 1) * 64;     // 2 col groups
    int q    = lane >> 3;
    int li   = lane & 7;
    int rowoff = (q & 1) * 8 + li;   // ldmatrix source row within 16
    int coloff = (q >> 1) * 8;       // ldmatrix source col within 16

    float acc[2][8][4];
#pragma unroll
    for (int mt = 0; mt < 2; mt++)
#pragma unroll
        for (int n = 0; n < 8; n++)
#pragma unroll
            for (int p = 0; p < 4; p++) acc[mt][n][p] = 0.f;

#pragma unroll
    for (int ks = 0; ks < 2; ks++) {
        unsigned ah[2][4], al[2][4];
#pragma unroll
        for (int mt = 0; mt < 2; mt++) {
            int off = (wm + mt * 16 + rowoff) * SROW + ks * 16 + coloff;
            ldx4(ah[mt], (unsigned)__cvta_generic_to_shared(&Ah[off]));
            ldx4(al[mt], (unsigned)__cvta_generic_to_shared(&Al[off]));
        }
#pragma unroll
        for (int nt = 0; nt < 4; nt++) {
            int off = (wn + nt * 16 + rowoff) * SROW + ks * 16 + coloff;
            unsigned bh[4], bl[4];
            ldx4(bh, (unsigned)__cvta_generic_to_shared(&Bh[off]));
            ldx4(bl, (unsigned)__cvta_generic_to_shared(&Bl[off]));
            // even n8 frag: {r0, r2}; odd n8 frag: {r1, r3}
#pragma unroll
            for (int mt = 0; mt < 2; mt++) {
                mma16816(acc[mt][2 * nt],     ah[mt], bh[0], bh[2]);
                mma16816(acc[mt][2 * nt],     ah[mt], bl[0], bl[2]);
                mma16816(acc[mt][2 * nt],     al[mt], bh[0], bh[2]);
                mma16816(acc[mt][2 * nt + 1], ah[mt], bh[1], bh[3]);
                mma16816(acc[mt][2 * nt + 1], ah[mt], bl[1], bl[3]);
                mma16816(acc[mt][2 * nt + 1], al[mt], bh[1], bh[3]);
            }
        }
    }

    // Epilogue: c0,c1 -> (row, col..col+1); c2,c3 -> (row+8, col..col+1)
    int g  = lane >> 2;
    int tg = lane & 3;
#pragma unroll
    for (int mt = 0; mt < 2; mt++) {
        int row0 = bi * 128 + wm + mt * 16 + g;
#pragma unroll
        for (int n = 0; n < 8; n++) {
            int col = bj * 128 + wn + n * 8 + tg * 2;
            float2* p0 = (float2*)(C + (size_t)row0 * NN + col);
            float2* p1 = (float2*)(C + (size_t)(row0 + 8) * NN + col);
            *p0 = make_float2(acc[mt][n][0], acc[mt][n][1]);
            *p1 = make_float2(acc[mt][n][2], acc[mt][n][3]);
        }
    }
}

// ---------------------------------------------------------------------------
extern "C" void kernel_launch(void* const* d_in, const int* in_sizes, int n_in,
                              void* d_out, int out_size) {
    const unsigned* xbuf  = (const unsigned*)d_in[0];
    const unsigned* eibuf = (const unsigned*)d_in[1];
    const float*    ea    = (const float*)d_in[2];
    const float*    emb   = (const float*)d_in[3];
    const float*    W1    = (const float*)d_in[4];
    const float*    b1    = (const float*)d_in[5];
    const float*    E1w   = (const float*)d_in[6];
    const float*    E1b   = (const float*)d_in[7];
    const float*    W2    = (const float*)d_in[8];
    const float*    b2    = (const float*)d_in[9];
    const float*    E2w   = (const float*)d_in[10];
    const float*    E2b   = (const float*)d_in[11];
    float* out = (float*)d_out;

    k_convert<<<(NE + 255) / 256, 256>>>(xbuf, eibuf);
    k_embed<<<NN * 32 / 256, 256>>>((const float4*)emb);
    k_edge1<<<2048, 256>>>((const float4*)ea,
                           (const float4*)E1w, (const float4*)E1b);
    k_lin1<<<NN / 4, 256>>>(W1, b1);
    k_edge2<<<2048, 256>>>((const float4*)ea,
                           (const float2*)E2w, (const float2*)E2b);
    k_lin2<<<NN / 8, 256>>>(W2, b2);
    dim3 g(NN / 128, NN / 128);
    k_gemm<<<g, 256>>>(out);
}

// round 7
// speedup vs baseline: 1.4342x; 1.2132x over previous
#include <cuda_runtime.h>
#include <cuda_bf16.h>

// GINE-conv network:
//   h = emb[x]; h = leaky_relu(gine(h, E1)); h2 = gine(h, E2); out = h2 @ h2.T
// N=8192, E=262144, dims 128 -> 64 -> 32, out 8192x8192 f32.
// R7: edge pass 1 edge-MLP moved to tensor cores (bf16 hi/lo, smem-fused),
//     rest identical to R6 (279us). k_prepw inserted so edge1 profiles at idx 3.

#define NN     8192
#define NE     262144
#define EMB    128
#define D1     64
#define D2     32
#define EPSF   1e-9f
#define SLOPEF 0.01f

__device__ __align__(16) float g_h[NN * EMB];
__device__ __align__(16) float g_agg1[NN * EMB];
__device__ __align__(16) float g_h1[NN * D1];
__device__ __align__(16) float g_agg2[NN * D1];
__device__ __align__(16) unsigned short g_h2hi[NN * D2];   // bf16 hi
__device__ __align__(16) unsigned short g_h2lo[NN * D2];   // bf16 lo residual
__device__ __align__(16) unsigned short g_w1hi[EMB * 16];  // E1w^T hi [n][k]
__device__ __align__(16) unsigned short g_w1lo[EMB * 16];  // E1w^T lo [n][k]
__device__ int g_x[NN];
__device__ int g_src[NE];
__device__ int g_dst[NE];

__device__ __forceinline__ void fma2s(float2& a, float s, const float2& w) {
    a.x = fmaf(s, w.x, a.x);
    a.y = fmaf(s, w.y, a.y);
}

__device__ __forceinline__ void ldx4(unsigned r[4], unsigned addr) {
    asm volatile("ldmatrix.sync.aligned.m8n8.x4.shared.b16 {%0,%1,%2,%3}, [%4];"
                 : "=r"(r[0]), "=r"(r[1]), "=r"(r[2]), "=r"(r[3]) : "r"(addr));
}
__device__ __forceinline__ void mma16816(float c[4], const unsigned a[4],
                                         unsigned b0, unsigned b1) {
    asm volatile(
        "mma.sync.aligned.m16n8k16.row.col.f32.bf16.bf16.f32 "
        "{%0,%1,%2,%3}, {%4,%5,%6,%7}, {%8,%9}, {%0,%1,%2,%3};"
        : "+f"(c[0]), "+f"(c[1]), "+f"(c[2]), "+f"(c[3])
        : "r"(a[0]), "r"(a[1]), "r"(a[2]), "r"(a[3]), "r"(b0), "r"(b1));
}

// ---------------------------------------------------------------------------
// K0: normalize index dtypes (int64 vs int32 delivery; detection as before).
// ---------------------------------------------------------------------------
__global__ void k_convert(const unsigned* __restrict__ xbuf,
                          const unsigned* __restrict__ eibuf) {
    unsigned odd_or = 0;
#pragma unroll
    for (int i = 0; i < 32; i++) odd_or |= eibuf[2 * i + 1];
    bool mode64 = (odd_or == 0);

    int t = blockIdx.x * blockDim.x + threadIdx.x;
    if (t < NE) {
        g_src[t] = (int)(mode64 ? eibuf[2 * t]        : eibuf[t]);
        g_dst[t] = (int)(mode64 ? eibuf[2 * (NE + t)] : eibuf[NE + t]);
    }
    if (t < NN) g_x[t] = (int)(mode64 ? xbuf[2 * t] : xbuf[t]);
}

// ---------------------------------------------------------------------------
// K1: h = emb[x];  agg1 = (1+eps)*h
// ---------------------------------------------------------------------------
__global__ void k_embed(const float4* __restrict__ emb4) {
    int t = blockIdx.x * blockDim.x + threadIdx.x;
    int node = t >> 5;
    int c    = t & 31;
    float4 v = emb4[g_x[node] * 32 + c];
    ((float4*)g_h)[t] = v;
    float4 a = make_float4(v.x * (1.f + EPSF), v.y * (1.f + EPSF),
                           v.z * (1.f + EPSF), v.w * (1.f + EPSF));
    ((float4*)g_agg1)[t] = a;
}

// ---------------------------------------------------------------------------
// K-prepw: Wt_hi/lo[n][k] = bf16 split of E1w[k][n]  (128 x 16 transposed).
// Also placed so that k_edge1 lands on ncu's profiled launch index (3).
// ---------------------------------------------------------------------------
__global__ void k_prepw(const float* __restrict__ E1w) {
    int t = blockIdx.x * blockDim.x + threadIdx.x;   // 0..2047
    int n = t >> 4;
    int k = t & 15;
    float w = E1w[k * EMB + n];
    __nv_bfloat16 hi = __float2bfloat16_rn(w);
    float res = w - __bfloat162float(hi);
    __nv_bfloat16 lo = __float2bfloat16_rn(res);
    g_w1hi[t] = *(unsigned short*)&hi;
    g_w1lo[t] = *(unsigned short*)&lo;
}

// ---------------------------------------------------------------------------
// K2: edge pass 1. Block = 64-edge tile.
// Phase A: ee[64][128] = ea_tile @ E1w via bf16 hi/lo mma (3 products) -> smem
// Phase B: warp per edge: m = relu(h[src] + ee + b); red.v4 into agg1[dst].
// ---------------------------------------------------------------------------
#define ET   64        // edges per tile
#define EESTRIDE 132   // fp32 row stride for ee (528B, 16B aligned)

__global__ void __launch_bounds__(256)
k_edge1(const float4* __restrict__ ea4,
        const float4* __restrict__ b4) {   // E1b as 32 float4
    __shared__ __align__(16) unsigned short sEaH[ET][16];
    __shared__ __align__(16) unsigned short sEaL[ET][16];
    __shared__ __align__(16) unsigned short sWtH[EMB][16];
    __shared__ __align__(16) unsigned short sWtL[EMB][16];
    __shared__ __align__(16) float sEe[ET][EESTRIDE];

    int tid  = threadIdx.x;
    int lane = tid & 31;
    int w    = tid >> 5;
    int tile = blockIdx.x;
    int e0   = tile * ET;

    float4 bias = b4[lane];

    // Stage weights (hi/lo): 1024 u32 each.
    {
        const unsigned* wh = (const unsigned*)g_w1hi;
        const unsigned* wl = (const unsigned*)g_w1lo;
        unsigned* dh = (unsigned*)sWtH;
        unsigned* dl = (unsigned*)sWtL;
        for (int i = tid; i < EMB * 8; i += 256) { dh[i] = wh[i]; dl[i] = wl[i]; }
    }
    // Stage + split edge_attr tile: 64 edges x 16 floats.
    {
        int el = tid >> 2;          // 0..63
        int pt = tid & 3;           // 0..3 (4 floats each)
        float4 v = ea4[(size_t)(e0 + el) * 4 + pt];
        unsigned short h_[4], l_[4];
        float vv[4] = {v.x, v.y, v.z, v.w};
#pragma unroll
        for (int i = 0; i < 4; i++) {
            __nv_bfloat16 hi = __float2bfloat16_rn(vv[i]);
            float res = vv[i] - __bfloat162float(hi);
            __nv_bfloat16 lo = __float2bfloat16_rn(res);
            h_[i] = *(unsigned short*)&hi;
            l_[i] = *(unsigned short*)&lo;
        }
        *(uint2*)&sEaH[el][pt * 4] = *(uint2*)h_;
        *(uint2*)&sEaL[el][pt * 4] = *(uint2*)l_;
    }
    __syncthreads();

    // Phase A: warp (w>>1 -> m16 group of 4, w&1 -> 64-col half)
    {
        int wm = (w >> 1) * 16;
        int wn = (w & 1) * 64;
        int q  = lane >> 3;
        int li = lane & 7;
        int rowoff = (q & 1) * 8 + li;
        int coloff = (q >> 1) * 8;

        unsigned ah[4], al[4];
        ldx4(ah, (unsigned)__cvta_generic_to_shared(&sEaH[wm + rowoff][coloff]));
        ldx4(al, (unsigned)__cvta_generic_to_shared(&sEaL[wm + rowoff][coloff]));

        float acc[8][4];
#pragma unroll
        for (int n = 0; n < 8; n++)
#pragma unroll
            for (int p = 0; p < 4; p++) acc[n][p] = 0.f;

#pragma unroll
        for (int nt = 0; nt < 4; nt++) {
            unsigned bh[4], bl[4];
            ldx4(bh, (unsigned)__cvta_generic_to_shared(&sWtH[wn + nt * 16 + rowoff][coloff]));
            ldx4(bl, (unsigned)__cvta_generic_to_shared(&sWtL[wn + nt * 16 + rowoff][coloff]));
            mma16816(acc[2 * nt],     ah, bh[0], bh[2]);
            mma16816(acc[2 * nt],     ah, bl[0], bl[2]);
            mma16816(acc[2 * nt],     al, bh[0], bh[2]);
            mma16816(acc[2 * nt + 1], ah, bh[1], bh[3]);
            mma16816(acc[2 * nt + 1], ah, bl[1], bl[3]);
            mma16816(acc[2 * nt + 1], al, bh[1], bh[3]);
        }

        int g  = lane >> 2;
        int tg = lane & 3;
#pragma unroll
        for (int n = 0; n < 8; n++) {
            int col = wn + n * 8 + tg * 2;
            *(float2*)&sEe[wm + g][col]     = make_float2(acc[n][0], acc[n][1]);
            *(float2*)&sEe[wm + g + 8][col] = make_float2(acc[n][2], acc[n][3]);
        }
    }
    __syncthreads();

    // Phase B: warp per edge (8 warps x 8 iterations).
    const float4* h4 = (const float4*)g_h;
#pragma unroll
    for (int it = 0; it < ET / 8; it++) {
        int el = w * (ET / 8) + it;
        int e  = e0 + el;
        int src = g_src[e];
        int dst = g_dst[e];

        float4 ev = *(const float4*)&sEe[el][lane * 4];
        float4 hv = h4[src * 32 + lane];
        float m0 = fmaxf(hv.x + ev.x + bias.x, 0.f);
        float m1 = fmaxf(hv.y + ev.y + bias.y, 0.f);
        float m2 = fmaxf(hv.z + ev.z + bias.z, 0.f);
        float m3 = fmaxf(hv.w + ev.w + bias.w, 0.f);

        float* p = g_agg1 + (size_t)dst * EMB + lane * 4;
        asm volatile("red.global.add.v4.f32 [%0], {%1,%2,%3,%4};"
                     :: "l"(p), "f"(m0), "f"(m1), "f"(m2), "f"(m3)
                     : "memory");
    }
}

// ---------------------------------------------------------------------------
// K3: h1 = leaky_relu(agg1 @ W1 + b1);  agg2 = (1+eps)*h1  (R2 version)
// ---------------------------------------------------------------------------
__global__ void __launch_bounds__(256)
k_lin1(const float* __restrict__ W1, const float* __restrict__ b1) {
    __shared__ float sW[EMB * D1];     // 32 KB
    __shared__ float srow[4 * EMB];    // 2 KB
    int tid = threadIdx.x;
    for (int i = tid; i < EMB * D1; i += 256) sW[i] = W1[i];
    int node0 = blockIdx.x * 4;
    for (int i = tid; i < 4 * EMB; i += 256) srow[i] = g_agg1[node0 * EMB + i];
    __syncthreads();

    int ln = tid >> 6;     // 0..3
    int c  = tid & 63;
    const float* row = &srow[ln * EMB];
    float acc = b1[c];
#pragma unroll 8
    for (int k = 0; k < EMB; k++) acc = fmaf(row[k], sW[k * D1 + c], acc);
    float v = acc >= 0.f ? acc : SLOPEF * acc;
    int n = node0 + ln;
    g_h1[n * D1 + c]   = v;
    g_agg2[n * D1 + c] = (1.f + EPSF) * v;
}

// ---------------------------------------------------------------------------
// K4: edge pass 2 (R2-validated). Warp per edge; lane owns 2 cols.
// ---------------------------------------------------------------------------
__global__ void __launch_bounds__(256)
k_edge2(const float4* __restrict__ ea4,
        const float2* __restrict__ w2v,    // E2w as (16 x 32) float2
        const float2* __restrict__ b2v) {  // E2b as 32 float2
    int lane = threadIdx.x & 31;
    int warp = (blockIdx.x * blockDim.x + threadIdx.x) >> 5;
    int nw   = (gridDim.x * blockDim.x) >> 5;

    float2 w[16];
#pragma unroll
    for (int k = 0; k < 16; k++) w[k] = w2v[k * 32 + lane];
    float2 bias = b2v[lane];

    const float2* h2v = (const float2*)g_h1;

    for (int e = warp; e < NE; e += nw) {
        int src = g_src[e];
        int dst = g_dst[e];
        float4 ea0 = ea4[e * 4 + 0];
        float4 ea1 = ea4[e * 4 + 1];
        float4 ea2 = ea4[e * 4 + 2];
        float4 ea3 = ea4[e * 4 + 3];

        float2 acc = bias;
        fma2s(acc, ea0.x, w[0]);  fma2s(acc, ea0.y, w[1]);
        fma2s(acc, ea0.z, w[2]);  fma2s(acc, ea0.w, w[3]);
        fma2s(acc, ea1.x, w[4]);  fma2s(acc, ea1.y, w[5]);
        fma2s(acc, ea1.z, w[6]);  fma2s(acc, ea1.w, w[7]);
        fma2s(acc, ea2.x, w[8]);  fma2s(acc, ea2.y, w[9]);
        fma2s(acc, ea2.z, w[10]); fma2s(acc, ea2.w, w[11]);
        fma2s(acc, ea3.x, w[12]); fma2s(acc, ea3.y, w[13]);
        fma2s(acc, ea3.z, w[14]); fma2s(acc, ea3.w, w[15]);

        float2 hv = h2v[src * 32 + lane];
        float m0 = fmaxf(hv.x + acc.x, 0.f);
        float m1 = fmaxf(hv.y + acc.y, 0.f);

        float* p = g_agg2 + (size_t)dst * D1 + lane * 2;
        asm volatile("red.global.add.v2.f32 [%0], {%1,%2};"
                     :: "l"(p), "f"(m0), "f"(m1)
                     : "memory");
    }
}

// ---------------------------------------------------------------------------
// K5: h2 = agg2 @ W2 + b2, stored as bf16 hi + bf16 lo residual.
// ---------------------------------------------------------------------------
__global__ void __launch_bounds__(256)
k_lin2(const float* __restrict__ W2, const float* __restrict__ b2) {
    __shared__ float sW[D1][D2 + 1];
    __shared__ float srow[8][D1 + 4];

    int tid  = threadIdx.x;
    int warp = tid >> 5;
    int lane = tid & 31;

    for (int i = tid; i < D1 * D2; i += 256)
        sW[i >> 5][i & 31] = W2[i];

    int n = blockIdx.x * 8 + warp;
    float2 rv = *(const float2*)(g_agg2 + (size_t)n * D1 + lane * 2);
    srow[warp][lane * 2]     = rv.x;
    srow[warp][lane * 2 + 1] = rv.y;
    __syncthreads();

    float acc = b2[lane];
#pragma unroll
    for (int k = 0; k < D1; k++)
        acc = fmaf(srow[warp][k], sW[k][lane], acc);

    __nv_bfloat16 hi = __float2bfloat16_rn(acc);
    float res = acc - __bfloat162float(hi);
    __nv_bfloat16 lo = __float2bfloat16_rn(res);
    g_h2hi[(size_t)n * D2 + lane] = *(unsigned short*)&hi;
    g_h2lo[(size_t)n * D2 + lane] = *(unsigned short*)&lo;
}

// ---------------------------------------------------------------------------
// K6: C = h2 @ h2^T via bf16 tensor cores with hi/lo split (R6-validated).
// ---------------------------------------------------------------------------
#define SROW 40

__global__ void __launch_bounds__(256)
k_gemm(float* __restrict__ C) {
    __shared__ __align__(16) unsigned short Ah[128 * SROW];
    __shared__ __align__(16) unsigned short Al[128 * SROW];
    __shared__ __align__(16) unsigned short Bh[128 * SROW];
    __shared__ __align__(16) unsigned short Bl[128 * SROW];

    int bi = blockIdx.y;
    int bj = blockIdx.x;
    int tid = threadIdx.x;

    const unsigned* h2h = (const unsigned*)g_h2hi;
    const unsigned* h2l = (const unsigned*)g_h2lo;
    unsigned* Ah32 = (unsigned*)Ah;
    unsigned* Al32 = (unsigned*)Al;
    unsigned* Bh32 = (unsigned*)Bh;
    unsigned* Bl32 = (unsigned*)Bl;

    for (int idx = tid; idx < 128 * 16; idx += 256) {
        int r  = idx >> 4;
        int c2 = idx & 15;
        int sm = r * (SROW / 2) + c2;
        Ah32[sm] = h2h[(size_t)(bi * 128 + r) * 16 + c2];
        Al32[sm] = h2l[(size_t)(bi * 128 + r) * 16 + c2];
        Bh32[sm] = h2h[(size_t)(bj * 128 + r) * 16 + c2];
        Bl32[sm] = h2l[(size_t)(bj * 128 + r) * 16 + c2];
    }
    __syncthreads();

    int w    = tid >> 5;
    int lane = tid & 31;
    int wm   = (w >> 1) * 32;
    int wn   = (w & 1) * 64;
    int q    = lane >> 3;
    int li   = lane & 7;
    int rowoff = (q & 1) * 8 + li;
    int coloff = (q >> 1) * 8;

    float acc[2][8][4];
#pragma unroll
    for (int mt = 0; mt < 2; mt++)
#pragma unroll
        for (int n = 0; n < 8; n++)
#pragma unroll
            for (int p = 0; p < 4; p++) acc[mt][n][p] = 0.f;

#pragma unroll
    for (int ks = 0; ks < 2; ks++) {
        unsigned ah[2][4], al[2][4];
#pragma unroll
        for (int mt = 0; mt < 2; mt++) {
            int off = (wm + mt * 16 + rowoff) * SROW + ks * 16 + coloff;
            ldx4(ah[mt], (unsigned)__cvta_generic_to_shared(&Ah[off]));
            ldx4(al[mt], (unsigned)__cvta_generic_to_shared(&Al[off]));
        }
#pragma unroll
        for (int nt = 0; nt < 4; nt++) {
            int off = (wn + nt * 16 + rowoff) * SROW + ks * 16 + coloff;
            unsigned bh[4], bl[4];
            ldx4(bh, (unsigned)__cvta_generic_to_shared(&Bh[off]));
            ldx4(bl, (unsigned)__cvta_generic_to_shared(&Bl[off]));
#pragma unroll
            for (int mt = 0; mt < 2; mt++) {
                mma16816(acc[mt][2 * nt],     ah[mt], bh[0], bh[2]);
                mma16816(acc[mt][2 * nt],     ah[mt], bl[0], bl[2]);
                mma16816(acc[mt][2 * nt],     al[mt], bh[0], bh[2]);
                mma16816(acc[mt][2 * nt + 1], ah[mt], bh[1], bh[3]);
                mma16816(acc[mt][2 * nt + 1], ah[mt], bl[1], bl[3]);
                mma16816(acc[mt][2 * nt + 1], al[mt], bh[1], bh[3]);
            }
        }
    }

    int g  = lane >> 2;
    int tg = lane & 3;
#pragma unroll
    for (int mt = 0; mt < 2; mt++) {
        int row0 = bi * 128 + wm + mt * 16 + g;
#pragma unroll
        for (int n = 0; n < 8; n++) {
            int col = bj * 128 + wn + n * 8 + tg * 2;
            float2* p0 = (float2*)(C + (size_t)row0 * NN + col);
            float2* p1 = (float2*)(C + (size_t)(row0 + 8) * NN + col);
            *p0 = make_float2(acc[mt][n][0], acc[mt][n][1]);
            *p1 = make_float2(acc[mt][n][2], acc[mt][n][3]);
        }
    }
}

// ---------------------------------------------------------------------------
extern "C" void kernel_launch(void* const* d_in, const int* in_sizes, int n_in,
                              void* d_out, int out_size) {
    const unsigned* xbuf  = (const unsigned*)d_in[0];
    const unsigned* eibuf = (const unsigned*)d_in[1];
    const float*    ea    = (const float*)d_in[2];
    const float*    emb   = (const float*)d_in[3];
    const float*    W1    = (const float*)d_in[4];
    const float*    b1    = (const float*)d_in[5];
    const float*    E1w   = (const float*)d_in[6];
    const float*    E1b   = (const float*)d_in[7];
    const float*    W2    = (const float*)d_in[8];
    const float*    b2    = (const float*)d_in[9];
    const float*    E2w   = (const float*)d_in[10];
    const float*    E2b   = (const float*)d_in[11];
    float* out = (float*)d_out;

    k_convert<<<(NE + 255) / 256, 256>>>(xbuf, eibuf);      // idx 0
    k_embed<<<NN * 32 / 256, 256>>>((const float4*)emb);    // idx 1
    k_prepw<<<8, 256>>>(E1w);                               // idx 2
    k_edge1<<<NE / ET, 256>>>((const float4*)ea,            // idx 3 (profiled)
                              (const float4*)E1b);
    k_lin1<<<NN / 4, 256>>>(W1, b1);
    k_edge2<<<2048, 256>>>((const float4*)ea,
                           (const float2*)E2w, (const float2*)E2b);
    k_lin2<<<NN / 8, 256>>>(W2, b2);
    dim3 g(NN / 128, NN / 128);
    k_gemm<<<g, 256>>>(out);
}

// round 8
// speedup vs baseline: 1.4780x; 1.0305x over previous
#include <cuda_runtime.h>
#include <cuda_bf16.h>

// GINE-conv network:
//   h = emb[x]; h = leaky_relu(gine(h, E1)); h2 = gine(h, E2); out = h2 @ h2.T
// N=8192, E=262144, dims 128 -> 64 -> 32, out 8192x8192 f32.
// R8: tensorized edge-MLP for BOTH edge passes (bf16 hi/lo, smem-fused).
//     edge1/gemm identical to R7 (230us).

#define NN     8192
#define NE     262144
#define EMB    128
#define D1     64
#define D2     32
#define EPSF   1e-9f
#define SLOPEF 0.01f

__device__ __align__(16) float g_h[NN * EMB];
__device__ __align__(16) float g_agg1[NN * EMB];
__device__ __align__(16) float g_h1[NN * D1];
__device__ __align__(16) float g_agg2[NN * D1];
__device__ __align__(16) unsigned short g_h2hi[NN * D2];   // bf16 hi
__device__ __align__(16) unsigned short g_h2lo[NN * D2];   // bf16 lo residual
__device__ __align__(16) unsigned short g_w1hi[EMB * 16];  // E1w^T hi [n][k]
__device__ __align__(16) unsigned short g_w1lo[EMB * 16];  // E1w^T lo [n][k]
__device__ __align__(16) unsigned short g_w2hi[D1 * 16];   // E2w^T hi [n][k]
__device__ __align__(16) unsigned short g_w2lo[D1 * 16];   // E2w^T lo [n][k]
__device__ int g_x[NN];
__device__ int g_src[NE];
__device__ int g_dst[NE];

__device__ __forceinline__ void ldx4(unsigned r[4], unsigned addr) {
    asm volatile("ldmatrix.sync.aligned.m8n8.x4.shared.b16 {%0,%1,%2,%3}, [%4];"
                 : "=r"(r[0]), "=r"(r[1]), "=r"(r[2]), "=r"(r[3]) : "r"(addr));
}
__device__ __forceinline__ void mma16816(float c[4], const unsigned a[4],
                                         unsigned b0, unsigned b1) {
    asm volatile(
        "mma.sync.aligned.m16n8k16.row.col.f32.bf16.bf16.f32 "
        "{%0,%1,%2,%3}, {%4,%5,%6,%7}, {%8,%9}, {%0,%1,%2,%3};"
        : "+f"(c[0]), "+f"(c[1]), "+f"(c[2]), "+f"(c[3])
        : "r"(a[0]), "r"(a[1]), "r"(a[2]), "r"(a[3]), "r"(b0), "r"(b1));
}
__device__ __forceinline__ void bf16split(float v, unsigned short& h,
                                          unsigned short& l) {
    __nv_bfloat16 hi = __float2bfloat16_rn(v);
    float res = v - __bfloat162float(hi);
    __nv_bfloat16 lo = __float2bfloat16_rn(res);
    h = *(unsigned short*)&hi;
    l = *(unsigned short*)&lo;
}

// ---------------------------------------------------------------------------
// K0: normalize index dtypes (int64 vs int32 delivery; detection as before).
// ---------------------------------------------------------------------------
__global__ void k_convert(const unsigned* __restrict__ xbuf,
                          const unsigned* __restrict__ eibuf) {
    unsigned odd_or = 0;
#pragma unroll
    for (int i = 0; i < 32; i++) odd_or |= eibuf[2 * i + 1];
    bool mode64 = (odd_or == 0);

    int t = blockIdx.x * blockDim.x + threadIdx.x;
    if (t < NE) {
        g_src[t] = (int)(mode64 ? eibuf[2 * t]        : eibuf[t]);
        g_dst[t] = (int)(mode64 ? eibuf[2 * (NE + t)] : eibuf[NE + t]);
    }
    if (t < NN) g_x[t] = (int)(mode64 ? xbuf[2 * t] : xbuf[t]);
}

// ---------------------------------------------------------------------------
// K1: h = emb[x];  agg1 = (1+eps)*h
// ---------------------------------------------------------------------------
__global__ void k_embed(const float4* __restrict__ emb4) {
    int t = blockIdx.x * blockDim.x + threadIdx.x;
    int node = t >> 5;
    int c    = t & 31;
    float4 v = emb4[g_x[node] * 32 + c];
    ((float4*)g_h)[t] = v;
    float4 a = make_float4(v.x * (1.f + EPSF), v.y * (1.f + EPSF),
                           v.z * (1.f + EPSF), v.w * (1.f + EPSF));
    ((float4*)g_agg1)[t] = a;
}

// ---------------------------------------------------------------------------
// K-prepw: Wt_hi/lo[n][k] = bf16 split of E1w[k][n]  (128 x 16 transposed).
// ---------------------------------------------------------------------------
__global__ void k_prepw(const float* __restrict__ E1w) {
    int t = blockIdx.x * blockDim.x + threadIdx.x;   // 0..2047
    int n = t >> 4;
    int k = t & 15;
    unsigned short h, l;
    bf16split(E1w[k * EMB + n], h, l);
    g_w1hi[t] = h;
    g_w1lo[t] = l;
}

// K-prepw2: same for E2w (64 x 16 transposed).
__global__ void k_prepw2(const float* __restrict__ E2w) {
    int t = blockIdx.x * blockDim.x + threadIdx.x;   // 0..1023
    int n = t >> 4;
    int k = t & 15;
    unsigned short h, l;
    bf16split(E2w[k * D1 + n], h, l);
    g_w2hi[t] = h;
    g_w2lo[t] = l;
}

// ---------------------------------------------------------------------------
// K2: edge pass 1 (R7-validated). Block = 64-edge tile.
// Phase A: ee[64][128] = ea_tile @ E1w via bf16 hi/lo mma -> smem
// Phase B: warp per edge: m = relu(h[src] + ee + b); red.v4 into agg1[dst].
// ---------------------------------------------------------------------------
#define ET   64
#define EESTRIDE 132

__global__ void __launch_bounds__(256)
k_edge1(const float4* __restrict__ ea4,
        const float4* __restrict__ b4) {   // E1b as 32 float4
    __shared__ __align__(16) unsigned short sEaH[ET][16];
    __shared__ __align__(16) unsigned short sEaL[ET][16];
    __shared__ __align__(16) unsigned short sWtH[EMB][16];
    __shared__ __align__(16) unsigned short sWtL[EMB][16];
    __shared__ __align__(16) float sEe[ET][EESTRIDE];

    int tid  = threadIdx.x;
    int lane = tid & 31;
    int w    = tid >> 5;
    int e0   = blockIdx.x * ET;

    float4 bias = b4[lane];

    {
        const unsigned* wh = (const unsigned*)g_w1hi;
        const unsigned* wl = (const unsigned*)g_w1lo;
        unsigned* dh = (unsigned*)sWtH;
        unsigned* dl = (unsigned*)sWtL;
        for (int i = tid; i < EMB * 8; i += 256) { dh[i] = wh[i]; dl[i] = wl[i]; }
    }
    {
        int el = tid >> 2;
        int pt = tid & 3;
        float4 v = ea4[(size_t)(e0 + el) * 4 + pt];
        unsigned short h_[4], l_[4];
        float vv[4] = {v.x, v.y, v.z, v.w};
#pragma unroll
        for (int i = 0; i < 4; i++) bf16split(vv[i], h_[i], l_[i]);
        *(uint2*)&sEaH[el][pt * 4] = *(uint2*)h_;
        *(uint2*)&sEaL[el][pt * 4] = *(uint2*)l_;
    }
    __syncthreads();

    {
        int wm = (w >> 1) * 16;
        int wn = (w & 1) * 64;
        int q  = lane >> 3;
        int li = lane & 7;
        int rowoff = (q & 1) * 8 + li;
        int coloff = (q >> 1) * 8;

        unsigned ah[4], al[4];
        ldx4(ah, (unsigned)__cvta_generic_to_shared(&sEaH[wm + rowoff][coloff]));
        ldx4(al, (unsigned)__cvta_generic_to_shared(&sEaL[wm + rowoff][coloff]));

        float acc[8][4];
#pragma unroll
        for (int n = 0; n < 8; n++)
#pragma unroll
            for (int p = 0; p < 4; p++) acc[n][p] = 0.f;

#pragma unroll
        for (int nt = 0; nt < 4; nt++) {
            unsigned bh[4], bl[4];
            ldx4(bh, (unsigned)__cvta_generic_to_shared(&sWtH[wn + nt * 16 + rowoff][coloff]));
            ldx4(bl, (unsigned)__cvta_generic_to_shared(&sWtL[wn + nt * 16 + rowoff][coloff]));
            mma16816(acc[2 * nt],     ah, bh[0], bh[2]);
            mma16816(acc[2 * nt],     ah, bl[0], bl[2]);
            mma16816(acc[2 * nt],     al, bh[0], bh[2]);
            mma16816(acc[2 * nt + 1], ah, bh[1], bh[3]);
            mma16816(acc[2 * nt + 1], ah, bl[1], bl[3]);
            mma16816(acc[2 * nt + 1], al, bh[1], bh[3]);
        }

        int g  = lane >> 2;
        int tg = lane & 3;
#pragma unroll
        for (int n = 0; n < 8; n++) {
            int col = wn + n * 8 + tg * 2;
            *(float2*)&sEe[wm + g][col]     = make_float2(acc[n][0], acc[n][1]);
            *(float2*)&sEe[wm + g + 8][col] = make_float2(acc[n][2], acc[n][3]);
        }
    }
    __syncthreads();

    const float4* h4 = (const float4*)g_h;
#pragma unroll
    for (int it = 0; it < ET / 8; it++) {
        int el = w * (ET / 8) + it;
        int e  = e0 + el;
        int src = g_src[e];
        int dst = g_dst[e];

        float4 ev = *(const float4*)&sEe[el][lane * 4];
        float4 hv = h4[src * 32 + lane];
        float m0 = fmaxf(hv.x + ev.x + bias.x, 0.f);
        float m1 = fmaxf(hv.y + ev.y + bias.y, 0.f);
        float m2 = fmaxf(hv.z + ev.z + bias.z, 0.f);
        float m3 = fmaxf(hv.w + ev.w + bias.w, 0.f);

        float* p = g_agg1 + (size_t)dst * EMB + lane * 4;
        asm volatile("red.global.add.v4.f32 [%0], {%1,%2,%3,%4};"
                     :: "l"(p), "f"(m0), "f"(m1), "f"(m2), "f"(m3)
                     : "memory");
    }
}

// ---------------------------------------------------------------------------
// K3: h1 = leaky_relu(agg1 @ W1 + b1);  agg2 = (1+eps)*h1  (R2 version)
// ---------------------------------------------------------------------------
__global__ void __launch_bounds__(256)
k_lin1(const float* __restrict__ W1, const float* __restrict__ b1) {
    __shared__ float sW[EMB * D1];     // 32 KB
    __shared__ float srow[4 * EMB];    // 2 KB
    int tid = threadIdx.x;
    for (int i = tid; i < EMB * D1; i += 256) sW[i] = W1[i];
    int node0 = blockIdx.x * 4;
    for (int i = tid; i < 4 * EMB; i += 256) srow[i] = g_agg1[node0 * EMB + i];
    __syncthreads();

    int ln = tid >> 6;
    int c  = tid & 63;
    const float* row = &srow[ln * EMB];
    float acc = b1[c];
#pragma unroll 8
    for (int k = 0; k < EMB; k++) acc = fmaf(row[k], sW[k * D1 + c], acc);
    float v = acc >= 0.f ? acc : SLOPEF * acc;
    int n = node0 + ln;
    g_h1[n * D1 + c]   = v;
    g_agg2[n * D1 + c] = (1.f + EPSF) * v;
}

// ---------------------------------------------------------------------------
// K4: edge pass 2, tensorized. Block = 64-edge tile.
// Phase A: ee2[64][64] = ea_tile @ E2w via bf16 hi/lo mma -> smem
// Phase B: warp per edge: m = relu(h1[src] + ee2 + b); red.v2 into agg2[dst].
// ---------------------------------------------------------------------------
#define EESTRIDE2 68

__global__ void __launch_bounds__(256)
k_edge2(const float4* __restrict__ ea4,
        const float2* __restrict__ b2v) {  // E2b as 32 float2
    __shared__ __align__(16) unsigned short sEaH[ET][16];
    __shared__ __align__(16) unsigned short sEaL[ET][16];
    __shared__ __align__(16) unsigned short sW2H[D1][16];
    __shared__ __align__(16) unsigned short sW2L[D1][16];
    __shared__ __align__(16) float sEe[ET][EESTRIDE2];

    int tid  = threadIdx.x;
    int lane = tid & 31;
    int w    = tid >> 5;
    int e0   = blockIdx.x * ET;

    float2 bias = b2v[lane];

    {
        const unsigned* wh = (const unsigned*)g_w2hi;
        const unsigned* wl = (const unsigned*)g_w2lo;
        unsigned* dh = (unsigned*)sW2H;
        unsigned* dl = (unsigned*)sW2L;
        for (int i = tid; i < D1 * 8; i += 256) { dh[i] = wh[i]; dl[i] = wl[i]; }
    }
    {
        int el = tid >> 2;
        int pt = tid & 3;
        float4 v = ea4[(size_t)(e0 + el) * 4 + pt];
        unsigned short h_[4], l_[4];
        float vv[4] = {v.x, v.y, v.z, v.w};
#pragma unroll
        for (int i = 0; i < 4; i++) bf16split(vv[i], h_[i], l_[i]);
        *(uint2*)&sEaH[el][pt * 4] = *(uint2*)h_;
        *(uint2*)&sEaL[el][pt * 4] = *(uint2*)l_;
    }
    __syncthreads();

    // Phase A: warp (w>>1 -> m16 group of 4, w&1 -> 32-col half)
    {
        int wm = (w >> 1) * 16;
        int wn = (w & 1) * 32;
        int q  = lane >> 3;
        int li = lane & 7;
        int rowoff = (q & 1) * 8 + li;
        int coloff = (q >> 1) * 8;

        unsigned ah[4], al[4];
        ldx4(ah, (unsigned)__cvta_generic_to_shared(&sEaH[wm + rowoff][coloff]));
        ldx4(al, (unsigned)__cvta_generic_to_shared(&sEaL[wm + rowoff][coloff]));

        float acc[4][4];
#pragma unroll
        for (int n = 0; n < 4; n++)
#pragma unroll
            for (int p = 0; p < 4; p++) acc[n][p] = 0.f;

#pragma unroll
        for (int nt = 0; nt < 2; nt++) {
            unsigned bh[4], bl[4];
            ldx4(bh, (unsigned)__cvta_generic_to_shared(&sW2H[wn + nt * 16 + rowoff][coloff]));
            ldx4(bl, (unsigned)__cvta_generic_to_shared(&sW2L[wn + nt * 16 + rowoff][coloff]));
            mma16816(acc[2 * nt],     ah, bh[0], bh[2]);
            mma16816(acc[2 * nt],     ah, bl[0], bl[2]);
            mma16816(acc[2 * nt],     al, bh[0], bh[2]);
            mma16816(acc[2 * nt + 1], ah, bh[1], bh[3]);
            mma16816(acc[2 * nt + 1], ah, bl[1], bl[3]);
            mma16816(acc[2 * nt + 1], al, bh[1], bh[3]);
        }

        int g  = lane >> 2;
        int tg = lane & 3;
#pragma unroll
        for (int n = 0; n < 4; n++) {
            int col = wn + n * 8 + tg * 2;
            *(float2*)&sEe[wm + g][col]     = make_float2(acc[n][0], acc[n][1]);
            *(float2*)&sEe[wm + g + 8][col] = make_float2(acc[n][2], acc[n][3]);
        }
    }
    __syncthreads();

    // Phase B: warp per edge (8 warps x 8 iterations).
    const float2* h2v = (const float2*)g_h1;
#pragma unroll
    for (int it = 0; it < ET / 8; it++) {
        int el = w * (ET / 8) + it;
        int e  = e0 + el;
        int src = g_src[e];
        int dst = g_dst[e];

        float2 ev = *(const float2*)&sEe[el][lane * 2];
        float2 hv = h2v[src * 32 + lane];
        float m0 = fmaxf(hv.x + ev.x + bias.x, 0.f);
        float m1 = fmaxf(hv.y + ev.y + bias.y, 0.f);

        float* p = g_agg2 + (size_t)dst * D1 + lane * 2;
        asm volatile("red.global.add.v2.f32 [%0], {%1,%2};"
                     :: "l"(p), "f"(m0), "f"(m1)
                     : "memory");
    }
}

// ---------------------------------------------------------------------------
// K5: h2 = agg2 @ W2 + b2, stored as bf16 hi + bf16 lo residual.
// ---------------------------------------------------------------------------
__global__ void __launch_bounds__(256)
k_lin2(const float* __restrict__ W2, const float* __restrict__ b2) {
    __shared__ float sW[D1][D2 + 1];
    __shared__ float srow[8][D1 + 4];

    int tid  = threadIdx.x;
    int warp = tid >> 5;
    int lane = tid & 31;

    for (int i = tid; i < D1 * D2; i += 256)
        sW[i >> 5][i & 31] = W2[i];

    int n = blockIdx.x * 8 + warp;
    float2 rv = *(const float2*)(g_agg2 + (size_t)n * D1 + lane * 2);
    srow[warp][lane * 2]     = rv.x;
    srow[warp][lane * 2 + 1] = rv.y;
    __syncthreads();

    float acc = b2[lane];
#pragma unroll
    for (int k = 0; k < D1; k++)
        acc = fmaf(srow[warp][k], sW[k][lane], acc);

    unsigned short h, l;
    bf16split(acc, h, l);
    g_h2hi[(size_t)n * D2 + lane] = h;
    g_h2lo[(size_t)n * D2 + lane] = l;
}

// ---------------------------------------------------------------------------
// K6: C = h2 @ h2^T via bf16 tensor cores with hi/lo split (R6-validated).
// ---------------------------------------------------------------------------
#define SROW 40

__global__ void __launch_bounds__(256)
k_gemm(float* __restrict__ C) {
    __shared__ __align__(16) unsigned short Ah[128 * SROW];
    __shared__ __align__(16) unsigned short Al[128 * SROW];
    __shared__ __align__(16) unsigned short Bh[128 * SROW];
    __shared__ __align__(16) unsigned short Bl[128 * SROW];

    int bi = blockIdx.y;
    int bj = blockIdx.x;
    int tid = threadIdx.x;

    const unsigned* h2h = (const unsigned*)g_h2hi;
    const unsigned* h2l = (const unsigned*)g_h2lo;
    unsigned* Ah32 = (unsigned*)Ah;
    unsigned* Al32 = (unsigned*)Al;
    unsigned* Bh32 = (unsigned*)Bh;
    unsigned* Bl32 = (unsigned*)Bl;

    for (int idx = tid; idx < 128 * 16; idx += 256) {
        int r  = idx >> 4;
        int c2 = idx & 15;
        int sm = r * (SROW / 2) + c2;
        Ah32[sm] = h2h[(size_t)(bi * 128 + r) * 16 + c2];
        Al32[sm] = h2l[(size_t)(bi * 128 + r) * 16 + c2];
        Bh32[sm] = h2h[(size_t)(bj * 128 + r) * 16 + c2];
        Bl32[sm] = h2l[(size_t)(bj * 128 + r) * 16 + c2];
    }
    __syncthreads();

    int w    = tid >> 5;
    int lane = tid & 31;
    int wm   = (w >> 1) * 32;
    int wn   = (w & 1) * 64;
    int q    = lane >> 3;
    int li   = lane & 7;
    int rowoff = (q & 1) * 8 + li;
    int coloff = (q >> 1) * 8;

    float acc[2][8][4];
#pragma unroll
    for (int mt = 0; mt < 2; mt++)
#pragma unroll
        for (int n = 0; n < 8; n++)
#pragma unroll
            for (int p = 0; p < 4; p++) acc[mt][n][p] = 0.f;

#pragma unroll
    for (int ks = 0; ks < 2; ks++) {
        unsigned ah[2][4], al[2][4];
#pragma unroll
        for (int mt = 0; mt < 2; mt++) {
            int off = (wm + mt * 16 + rowoff) * SROW + ks * 16 + coloff;
            ldx4(ah[mt], (unsigned)__cvta_generic_to_shared(&Ah[off]));
            ldx4(al[mt], (unsigned)__cvta_generic_to_shared(&Al[off]));
        }
#pragma unroll
        for (int nt = 0; nt < 4; nt++) {
            int off = (wn + nt * 16 + rowoff) * SROW + ks * 16 + coloff;
            unsigned bh[4], bl[4];
            ldx4(bh, (unsigned)__cvta_generic_to_shared(&Bh[off]));
            ldx4(bl, (unsigned)__cvta_generic_to_shared(&Bl[off]));
#pragma unroll
            for (int mt = 0; mt < 2; mt++) {
                mma16816(acc[mt][2 * nt],     ah[mt], bh[0], bh[2]);
                mma16816(acc[mt][2 * nt],     ah[mt], bl[0], bl[2]);
                mma16816(acc[mt][2 * nt],     al[mt], bh[0], bh[2]);
                mma16816(acc[mt][2 * nt + 1], ah[mt], bh[1], bh[3]);
                mma16816(acc[mt][2 * nt + 1], ah[mt], bl[1], bl[3]);
                mma16816(acc[mt][2 * nt + 1], al[mt], bh[1], bh[3]);
            }
        }
    }

    int g  = lane >> 2;
    int tg = lane & 3;
#pragma unroll
    for (int mt = 0; mt < 2; mt++) {
        int row0 = bi * 128 + wm + mt * 16 + g;
#pragma unroll
        for (int n = 0; n < 8; n++) {
            int col = bj * 128 + wn + n * 8 + tg * 2;
            float2* p0 = (float2*)(C + (size_t)row0 * NN + col);
            float2* p1 = (float2*)(C + (size_t)(row0 + 8) * NN + col);
            *p0 = make_float2(acc[mt][n][0], acc[mt][n][1]);
            *p1 = make_float2(acc[mt][n][2], acc[mt][n][3]);
        }
    }
}

// ---------------------------------------------------------------------------
extern "C" void kernel_launch(void* const* d_in, const int* in_sizes, int n_in,
                              void* d_out, int out_size) {
    const unsigned* xbuf  = (const unsigned*)d_in[0];
    const unsigned* eibuf = (const unsigned*)d_in[1];
    const float*    ea    = (const float*)d_in[2];
    const float*    emb   = (const float*)d_in[3];
    const float*    W1    = (const float*)d_in[4];
    const float*    b1    = (const float*)d_in[5];
    const float*    E1w   = (const float*)d_in[6];
    const float*    E1b   = (const float*)d_in[7];
    const float*    W2    = (const float*)d_in[8];
    const float*    b2    = (const float*)d_in[9];
    const float*    E2w   = (const float*)d_in[10];
    const float*    E2b   = (const float*)d_in[11];
    float* out = (float*)d_out;

    k_convert<<<(NE + 255) / 256, 256>>>(xbuf, eibuf);      // idx 0
    k_embed<<<NN * 32 / 256, 256>>>((const float4*)emb);    // idx 1
    k_prepw<<<8, 256>>>(E1w);                               // idx 2
    k_edge1<<<NE / ET, 256>>>((const float4*)ea,            // idx 3 (profiled)
                              (const float4*)E1b);
    k_lin1<<<NN / 4, 256>>>(W1, b1);
    k_prepw2<<<4, 256>>>(E2w);
    k_edge2<<<NE / ET, 256>>>((const float4*)ea,
                              (const float2*)E2b);
    k_lin2<<<NN / 8, 256>>>(W2, b2);
    dim3 g(NN / 128, NN / 128);
    k_gemm<<<g, 256>>>(out);
}

// round 11
// speedup vs baseline: 1.7327x; 1.1724x over previous
#include <cuda_runtime.h>
#include <cuda_bf16.h>

// GINE-conv network:
//   h = emb[x]; h = leaky_relu(gine(h, E1)); h2 = gine(h, E2); out = h2 @ h2.T
// N=8192, E=262144, dims 128 -> 64 -> 32, out 8192x8192 f32.
// R11: R10 with k_lin1 Stage-B coverage bug fixed (staged 1024 of 2048 u32 of
//      the W1^T tile; uninitialized smem read as bf16 -> NaN). Changes vs R8
//      (223us): uint4 gemm staging + tensorized k_lin1 (stride 72, 16B-aligned).

#define NN     8192
#define NE     262144
#define EMB    128
#define D1     64
#define D2     32
#define EPSF   1e-9f
#define SLOPEF 0.01f

__device__ __align__(16) float g_h[NN * EMB];
__device__ __align__(16) float g_agg1[NN * EMB];
__device__ __align__(16) float g_h1[NN * D1];
__device__ __align__(16) float g_agg2[NN * D1];
__device__ __align__(16) unsigned short g_h2hi[NN * D2];   // bf16 hi
__device__ __align__(16) unsigned short g_h2lo[NN * D2];   // bf16 lo residual
__device__ __align__(16) unsigned short g_w1hi[EMB * 16];  // E1w^T hi [n][k]
__device__ __align__(16) unsigned short g_w1lo[EMB * 16];  // E1w^T lo [n][k]
__device__ __align__(16) unsigned short g_w2hi[D1 * 16];   // E2w^T hi [n][k]
__device__ __align__(16) unsigned short g_w2lo[D1 * 16];   // E2w^T lo [n][k]
__device__ __align__(16) unsigned short g_w1bh[D1 * EMB];  // W1^T hi [n][k]
__device__ __align__(16) unsigned short g_w1bl[D1 * EMB];  // W1^T lo [n][k]
__device__ int g_x[NN];
__device__ int g_src[NE];
__device__ int g_dst[NE];

__device__ __forceinline__ void ldx4(unsigned r[4], unsigned addr) {
    asm volatile("ldmatrix.sync.aligned.m8n8.x4.shared.b16 {%0,%1,%2,%3}, [%4];"
                 : "=r"(r[0]), "=r"(r[1]), "=r"(r[2]), "=r"(r[3]) : "r"(addr));
}
__device__ __forceinline__ void mma16816(float c[4], const unsigned a[4],
                                         unsigned b0, unsigned b1) {
    asm volatile(
        "mma.sync.aligned.m16n8k16.row.col.f32.bf16.bf16.f32 "
        "{%0,%1,%2,%3}, {%4,%5,%6,%7}, {%8,%9}, {%0,%1,%2,%3};"
        : "+f"(c[0]), "+f"(c[1]), "+f"(c[2]), "+f"(c[3])
        : "r"(a[0]), "r"(a[1]), "r"(a[2]), "r"(a[3]), "r"(b0), "r"(b1));
}
__device__ __forceinline__ void bf16split(float v, unsigned short& h,
                                          unsigned short& l) {
    __nv_bfloat16 hi = __float2bfloat16_rn(v);
    float res = v - __bfloat162float(hi);
    __nv_bfloat16 lo = __float2bfloat16_rn(res);
    h = *(unsigned short*)&hi;
    l = *(unsigned short*)&lo;
}

// ---------------------------------------------------------------------------
// K0: normalize index dtypes (int64 vs int32 delivery; detection as before).
// ---------------------------------------------------------------------------
__global__ void k_convert(const unsigned* __restrict__ xbuf,
                          const unsigned* __restrict__ eibuf) {
    unsigned odd_or = 0;
#pragma unroll
    for (int i = 0; i < 32; i++) odd_or |= eibuf[2 * i + 1];
    bool mode64 = (odd_or == 0);

    int t = blockIdx.x * blockDim.x + threadIdx.x;
    if (t < NE) {
        g_src[t] = (int)(mode64 ? eibuf[2 * t]        : eibuf[t]);
        g_dst[t] = (int)(mode64 ? eibuf[2 * (NE + t)] : eibuf[NE + t]);
    }
    if (t < NN) g_x[t] = (int)(mode64 ? xbuf[2 * t] : xbuf[t]);
}

// ---------------------------------------------------------------------------
// K1: h = emb[x];  agg1 = (1+eps)*h
// ---------------------------------------------------------------------------
__global__ void k_embed(const float4* __restrict__ emb4) {
    int t = blockIdx.x * blockDim.x + threadIdx.x;
    int node = t >> 5;
    int c    = t & 31;
    float4 v = emb4[g_x[node] * 32 + c];
    ((float4*)g_h)[t] = v;
    float4 a = make_float4(v.x * (1.f + EPSF), v.y * (1.f + EPSF),
                           v.z * (1.f + EPSF), v.w * (1.f + EPSF));
    ((float4*)g_agg1)[t] = a;
}

// ---------------------------------------------------------------------------
// Weight prep kernels (bf16 hi/lo transposed splits).
// ---------------------------------------------------------------------------
__global__ void k_prepw(const float* __restrict__ E1w) {
    int t = blockIdx.x * blockDim.x + threadIdx.x;   // 0..2047
    int n = t >> 4;
    int k = t & 15;
    unsigned short h, l;
    bf16split(E1w[k * EMB + n], h, l);
    g_w1hi[t] = h;
    g_w1lo[t] = l;
}

__global__ void k_prepw2(const float* __restrict__ E2w) {
    int t = blockIdx.x * blockDim.x + threadIdx.x;   // 0..1023
    int n = t >> 4;
    int k = t & 15;
    unsigned short h, l;
    bf16split(E2w[k * D1 + n], h, l);
    g_w2hi[t] = h;
    g_w2lo[t] = l;
}

// W1 [128 k][64 n] -> W1^T hi/lo [64 n][128 k]
__global__ void k_prepw1(const float* __restrict__ W1) {
    int t = blockIdx.x * blockDim.x + threadIdx.x;   // 0..8191
    int n = t >> 7;
    int kk = t & 127;
    unsigned short h, l;
    bf16split(W1[kk * D1 + n], h, l);
    g_w1bh[t] = h;
    g_w1bl[t] = l;
}

// ---------------------------------------------------------------------------
// K2: edge pass 1 (R7-validated). Block = 64-edge tile.
// ---------------------------------------------------------------------------
#define ET   64
#define EESTRIDE 132

__global__ void __launch_bounds__(256)
k_edge1(const float4* __restrict__ ea4,
        const float4* __restrict__ b4) {   // E1b as 32 float4
    __shared__ __align__(16) unsigned short sEaH[ET][16];
    __shared__ __align__(16) unsigned short sEaL[ET][16];
    __shared__ __align__(16) unsigned short sWtH[EMB][16];
    __shared__ __align__(16) unsigned short sWtL[EMB][16];
    __shared__ __align__(16) float sEe[ET][EESTRIDE];

    int tid  = threadIdx.x;
    int lane = tid & 31;
    int w    = tid >> 5;
    int e0   = blockIdx.x * ET;

    float4 bias = b4[lane];

    {
        const unsigned* wh = (const unsigned*)g_w1hi;
        const unsigned* wl = (const unsigned*)g_w1lo;
        unsigned* dh = (unsigned*)sWtH;
        unsigned* dl = (unsigned*)sWtL;
        for (int i = tid; i < EMB * 8; i += 256) { dh[i] = wh[i]; dl[i] = wl[i]; }
    }
    {
        int el = tid >> 2;
        int pt = tid & 3;
        float4 v = ea4[(size_t)(e0 + el) * 4 + pt];
        unsigned short h_[4], l_[4];
        float vv[4] = {v.x, v.y, v.z, v.w};
#pragma unroll
        for (int i = 0; i < 4; i++) bf16split(vv[i], h_[i], l_[i]);
        *(uint2*)&sEaH[el][pt * 4] = *(uint2*)h_;
        *(uint2*)&sEaL[el][pt * 4] = *(uint2*)l_;
    }
    __syncthreads();

    {
        int wm = (w >> 1) * 16;
        int wn = (w & 1) * 64;
        int q  = lane >> 3;
        int li = lane & 7;
        int rowoff = (q & 1) * 8 + li;
        int coloff = (q >> 1) * 8;

        unsigned ah[4], al[4];
        ldx4(ah, (unsigned)__cvta_generic_to_shared(&sEaH[wm + rowoff][coloff]));
        ldx4(al, (unsigned)__cvta_generic_to_shared(&sEaL[wm + rowoff][coloff]));

        float acc[8][4];
#pragma unroll
        for (int n = 0; n < 8; n++)
#pragma unroll
            for (int p = 0; p < 4; p++) acc[n][p] = 0.f;

#pragma unroll
        for (int nt = 0; nt < 4; nt++) {
            unsigned bh[4], bl[4];
            ldx4(bh, (unsigned)__cvta_generic_to_shared(&sWtH[wn + nt * 16 + rowoff][coloff]));
            ldx4(bl, (unsigned)__cvta_generic_to_shared(&sWtL[wn + nt * 16 + rowoff][coloff]));
            mma16816(acc[2 * nt],     ah, bh[0], bh[2]);
            mma16816(acc[2 * nt],     ah, bl[0], bl[2]);
            mma16816(acc[2 * nt],     al, bh[0], bh[2]);
            mma16816(acc[2 * nt + 1], ah, bh[1], bh[3]);
            mma16816(acc[2 * nt + 1], ah, bl[1], bl[3]);
            mma16816(acc[2 * nt + 1], al, bh[1], bh[3]);
        }

        int g  = lane >> 2;
        int tg = lane & 3;
#pragma unroll
        for (int n = 0; n < 8; n++) {
            int col = wn + n * 8 + tg * 2;
            *(float2*)&sEe[wm + g][col]     = make_float2(acc[n][0], acc[n][1]);
            *(float2*)&sEe[wm + g + 8][col] = make_float2(acc[n][2], acc[n][3]);
        }
    }
    __syncthreads();

    const float4* h4 = (const float4*)g_h;
#pragma unroll
    for (int it = 0; it < ET / 8; it++) {
        int el = w * (ET / 8) + it;
        int e  = e0 + el;
        int src = g_src[e];
        int dst = g_dst[e];

        float4 ev = *(const float4*)&sEe[el][lane * 4];
        float4 hv = h4[src * 32 + lane];
        float m0 = fmaxf(hv.x + ev.x + bias.x, 0.f);
        float m1 = fmaxf(hv.y + ev.y + bias.y, 0.f);
        float m2 = fmaxf(hv.z + ev.z + bias.z, 0.f);
        float m3 = fmaxf(hv.w + ev.w + bias.w, 0.f);

        float* p = g_agg1 + (size_t)dst * EMB + lane * 4;
        asm volatile("red.global.add.v4.f32 [%0], {%1,%2,%3,%4};"
                     :: "l"(p), "f"(m0), "f"(m1), "f"(m2), "f"(m3)
                     : "memory");
    }
}

// ---------------------------------------------------------------------------
// K3: h1 = leaky_relu(agg1 @ W1 + b1); agg2 = (1+eps)*h1.  TENSORIZED.
// Block = 64 nodes, 8 warps (4m x 2n), warp tile 16x32. K=128 in two halves.
// Smem stride 72 u16 = 144B (16B multiple: ldmatrix-legal, conflict-free).
// ---------------------------------------------------------------------------
#define L1S 72

__global__ void __launch_bounds__(256)
k_lin1(const float* __restrict__ b1) {
    __shared__ __align__(16) unsigned short sAh[64][L1S];
    __shared__ __align__(16) unsigned short sAl[64][L1S];
    __shared__ __align__(16) unsigned short sBh[64][L1S];
    __shared__ __align__(16) unsigned short sBl[64][L1S];

    int tid  = threadIdx.x;
    int lane = tid & 31;
    int w    = tid >> 5;
    int node0 = blockIdx.x * 64;

    int wm = (w >> 1) * 16;
    int wn = (w & 1) * 32;
    int q  = lane >> 3;
    int li = lane & 7;
    int rowoff = (q & 1) * 8 + li;
    int coloff = (q >> 1) * 8;
    int g  = lane >> 2;
    int tg = lane & 3;

    // acc init with bias (added once; accumulates across k-halves)
    float acc[4][4];
#pragma unroll
    for (int n = 0; n < 4; n++) {
        int col = wn + n * 8 + tg * 2;
        float bb0 = b1[col];
        float bb1 = b1[col + 1];
        acc[n][0] = bb0; acc[n][1] = bb1;
        acc[n][2] = bb0; acc[n][3] = bb1;
    }

    const unsigned* wb_h = (const unsigned*)g_w1bh;   // [64 n][64 u32]
    const unsigned* wb_l = (const unsigned*)g_w1bl;

#pragma unroll
    for (int kh = 0; kh < 2; kh++) {
        if (kh) __syncthreads();
        // Stage A: 64 nodes x 64 k fp32 -> bf16 hi/lo  (1024 float4-quarters)
#pragma unroll
        for (int i = 0; i < 4; i++) {
            int lin = tid + i * 256;          // 0..1023
            int nd  = lin >> 4;
            int c4  = lin & 15;
            float4 v = *(const float4*)&g_agg1[(size_t)(node0 + nd) * EMB + kh * 64 + c4 * 4];
            unsigned short h_[4], l_[4];
            float vv[4] = {v.x, v.y, v.z, v.w};
#pragma unroll
            for (int j = 0; j < 4; j++) bf16split(vv[j], h_[j], l_[j]);
            *(uint2*)&sAh[nd][c4 * 4] = *(uint2*)h_;
            *(uint2*)&sAl[nd][c4 * 4] = *(uint2*)l_;
        }
        // Stage B: W1^T hi/lo [64 n][this k-half: 32 u32 = 64 bf16]  (2048 u32)
#pragma unroll
        for (int i = 0; i < 8; i++) {
            int lin = tid + i * 256;          // 0..2047
            int n   = lin >> 5;               // 0..63
            int c2  = lin & 31;               // 0..31
            ((unsigned*)&sBh[n][c2 * 2])[0] = wb_h[n * 64 + kh * 32 + c2];
            ((unsigned*)&sBl[n][c2 * 2])[0] = wb_l[n * 64 + kh * 32 + c2];
        }
        __syncthreads();

#pragma unroll
        for (int ks = 0; ks < 4; ks++) {
            unsigned ah[4], al[4];
            ldx4(ah, (unsigned)__cvta_generic_to_shared(&sAh[wm + rowoff][ks * 16 + coloff]));
            ldx4(al, (unsigned)__cvta_generic_to_shared(&sAl[wm + rowoff][ks * 16 + coloff]));
#pragma unroll
            for (int nt = 0; nt < 2; nt++) {
                unsigned bh[4], bl[4];
                ldx4(bh, (unsigned)__cvta_generic_to_shared(&sBh[wn + nt * 16 + rowoff][ks * 16 + coloff]));
                ldx4(bl, (unsigned)__cvta_generic_to_shared(&sBl[wn + nt * 16 + rowoff][ks * 16 + coloff]));
                mma16816(acc[2 * nt],     ah, bh[0], bh[2]);
                mma16816(acc[2 * nt],     ah, bl[0], bl[2]);
                mma16816(acc[2 * nt],     al, bh[0], bh[2]);
                mma16816(acc[2 * nt + 1], ah, bh[1], bh[3]);
                mma16816(acc[2 * nt + 1], ah, bl[1], bl[3]);
                mma16816(acc[2 * nt + 1], al, bh[1], bh[3]);
            }
        }
    }

    // Epilogue: leaky_relu -> h1; (1+eps)*h1 -> agg2
#pragma unroll
    for (int n = 0; n < 4; n++) {
        int col = wn + n * 8 + tg * 2;
        float v0 = acc[n][0], v1 = acc[n][1], v2 = acc[n][2], v3 = acc[n][3];
        float a0 = v0 >= 0.f ? v0 : SLOPEF * v0;
        float a1 = v1 >= 0.f ? v1 : SLOPEF * v1;
        float a2 = v2 >= 0.f ? v2 : SLOPEF * v2;
        float a3 = v3 >= 0.f ? v3 : SLOPEF * v3;
        size_t r0 = (size_t)(node0 + wm + g) * D1 + col;
        size_t r1 = (size_t)(node0 + wm + g + 8) * D1 + col;
        *(float2*)&g_h1[r0]   = make_float2(a0, a1);
        *(float2*)&g_h1[r1]   = make_float2(a2, a3);
        *(float2*)&g_agg2[r0] = make_float2((1.f + EPSF) * a0, (1.f + EPSF) * a1);
        *(float2*)&g_agg2[r1] = make_float2((1.f + EPSF) * a2, (1.f + EPSF) * a3);
    }
}

// ---------------------------------------------------------------------------
// K4: edge pass 2, tensorized (R8-validated). Block = 64-edge tile.
// ---------------------------------------------------------------------------
#define EESTRIDE2 68

__global__ void __launch_bounds__(256)
k_edge2(const float4* __restrict__ ea4,
        const float2* __restrict__ b2v) {  // E2b as 32 float2
    __shared__ __align__(16) unsigned short sEaH[ET][16];
    __shared__ __align__(16) unsigned short sEaL[ET][16];
    __shared__ __align__(16) unsigned short sW2H[D1][16];
    __shared__ __align__(16) unsigned short sW2L[D1][16];
    __shared__ __align__(16) float sEe[ET][EESTRIDE2];

    int tid  = threadIdx.x;
    int lane = tid & 31;
    int w    = tid >> 5;
    int e0   = blockIdx.x * ET;

    float2 bias = b2v[lane];

    {
        const unsigned* wh = (const unsigned*)g_w2hi;
        const unsigned* wl = (const unsigned*)g_w2lo;
        unsigned* dh = (unsigned*)sW2H;
        unsigned* dl = (unsigned*)sW2L;
        for (int i = tid; i < D1 * 8; i += 256) { dh[i] = wh[i]; dl[i] = wl[i]; }
    }
    {
        int el = tid >> 2;
        int pt = tid & 3;
        float4 v = ea4[(size_t)(e0 + el) * 4 + pt];
        unsigned short h_[4], l_[4];
        float vv[4] = {v.x, v.y, v.z, v.w};
#pragma unroll
        for (int i = 0; i < 4; i++) bf16split(vv[i], h_[i], l_[i]);
        *(uint2*)&sEaH[el][pt * 4] = *(uint2*)h_;
        *(uint2*)&sEaL[el][pt * 4] = *(uint2*)l_;
    }
    __syncthreads();

    {
        int wm = (w >> 1) * 16;
        int wn = (w & 1) * 32;
        int q  = lane >> 3;
        int li = lane & 7;
        int rowoff = (q & 1) * 8 + li;
        int coloff = (q >> 1) * 8;

        unsigned ah[4], al[4];
        ldx4(ah, (unsigned)__cvta_generic_to_shared(&sEaH[wm + rowoff][coloff]));
        ldx4(al, (unsigned)__cvta_generic_to_shared(&sEaL[wm + rowoff][coloff]));

        float acc[4][4];
#pragma unroll
        for (int n = 0; n < 4; n++)
#pragma unroll
            for (int p = 0; p < 4; p++) acc[n][p] = 0.f;

#pragma unroll
        for (int nt = 0; nt < 2; nt++) {
            unsigned bh[4], bl[4];
            ldx4(bh, (unsigned)__cvta_generic_to_shared(&sW2H[wn + nt * 16 + rowoff][coloff]));
            ldx4(bl, (unsigned)__cvta_generic_to_shared(&sW2L[wn + nt * 16 + rowoff][coloff]));
            mma16816(acc[2 * nt],     ah, bh[0], bh[2]);
            mma16816(acc[2 * nt],     ah, bl[0], bl[2]);
            mma16816(acc[2 * nt],     al, bh[0], bh[2]);
            mma16816(acc[2 * nt + 1], ah, bh[1], bh[3]);
            mma16816(acc[2 * nt + 1], ah, bl[1], bl[3]);
            mma16816(acc[2 * nt + 1], al, bh[1], bh[3]);
        }

        int g  = lane >> 2;
        int tg = lane & 3;
#pragma unroll
        for (int n = 0; n < 4; n++) {
            int col = wn + n * 8 + tg * 2;
            *(float2*)&sEe[wm + g][col]     = make_float2(acc[n][0], acc[n][1]);
            *(float2*)&sEe[wm + g + 8][col] = make_float2(acc[n][2], acc[n][3]);
        }
    }
    __syncthreads();

    const float2* h2v = (const float2*)g_h1;
#pragma unroll
    for (int it = 0; it < ET / 8; it++) {
        int el = w * (ET / 8) + it;
        int e  = e0 + el;
        int src = g_src[e];
        int dst = g_dst[e];

        float2 ev = *(const float2*)&sEe[el][lane * 2];
        float2 hv = h2v[src * 32 + lane];
        float m0 = fmaxf(hv.x + ev.x + bias.x, 0.f);
        float m1 = fmaxf(hv.y + ev.y + bias.y, 0.f);

        float* p = g_agg2 + (size_t)dst * D1 + lane * 2;
        asm volatile("red.global.add.v2.f32 [%0], {%1,%2};"
                     :: "l"(p), "f"(m0), "f"(m1)
                     : "memory");
    }
}

// ---------------------------------------------------------------------------
// K5: h2 = agg2 @ W2 + b2, stored as bf16 hi + bf16 lo residual.
// ---------------------------------------------------------------------------
__global__ void __launch_bounds__(256)
k_lin2(const float* __restrict__ W2, const float* __restrict__ b2) {
    __shared__ float sW[D1][D2 + 1];
    __shared__ float srow[8][D1 + 4];

    int tid  = threadIdx.x;
    int warp = tid >> 5;
    int lane = tid & 31;

    for (int i = tid; i < D1 * D2; i += 256)
        sW[i >> 5][i & 31] = W2[i];

    int n = blockIdx.x * 8 + warp;
    float2 rv = *(const float2*)(g_agg2 + (size_t)n * D1 + lane * 2);
    srow[warp][lane * 2]     = rv.x;
    srow[warp][lane * 2 + 1] = rv.y;
    __syncthreads();

    float acc = b2[lane];
#pragma unroll
    for (int k = 0; k < D1; k++)
        acc = fmaf(srow[warp][k], sW[k][lane], acc);

    unsigned short h, l;
    bf16split(acc, h, l);
    g_h2hi[(size_t)n * D2 + lane] = h;
    g_h2lo[(size_t)n * D2 + lane] = l;
}

// ---------------------------------------------------------------------------
// K6: C = h2 @ h2^T via bf16 tensor cores (R6-validated), uint4 staging.
// ---------------------------------------------------------------------------
#define SROW 40

__global__ void __launch_bounds__(256)
k_gemm(float* __restrict__ C) {
    __shared__ __align__(16) unsigned short Ah[128 * SROW];
    __shared__ __align__(16) unsigned short Al[128 * SROW];
    __shared__ __align__(16) unsigned short Bh[128 * SROW];
    __shared__ __align__(16) unsigned short Bl[128 * SROW];

    int bi = blockIdx.y;
    int bj = blockIdx.x;
    int tid = threadIdx.x;

    // Stage tiles as uint4: row = 4 uint4 in gmem (64B), 5 uint4 stride in smem.
    {
        const uint4* h2h4 = (const uint4*)g_h2hi;
        const uint4* h2l4 = (const uint4*)g_h2lo;
        uint4* Ah4 = (uint4*)Ah;
        uint4* Al4 = (uint4*)Al;
        uint4* Bh4 = (uint4*)Bh;
        uint4* Bl4 = (uint4*)Bl;
#pragma unroll
        for (int i = 0; i < 2; i++) {
            int idx = tid + i * 256;       // 0..511
            int r = idx >> 2;
            int q = idx & 3;
            int sm = r * 5 + q;
            Ah4[sm] = h2h4[(size_t)(bi * 128 + r) * 4 + q];
            Al4[sm] = h2l4[(size_t)(bi * 128 + r) * 4 + q];
            Bh4[sm] = h2h4[(size_t)(bj * 128 + r) * 4 + q];
            Bl4[sm] = h2l4[(size_t)(bj * 128 + r) * 4 + q];
        }
    }
    __syncthreads();

    int w    = tid >> 5;
    int lane = tid & 31;
    int wm   = (w >> 1) * 32;
    int wn   = (w & 1) * 64;
    int q    = lane >> 3;
    int li   = lane & 7;
    int rowoff = (q & 1) * 8 + li;
    int coloff = (q >> 1) * 8;

    float acc[2][8][4];
#pragma unroll
    for (int mt = 0; mt < 2; mt++)
#pragma unroll
        for (int n = 0; n < 8; n++)
#pragma unroll
            for (int p = 0; p < 4; p++) acc[mt][n][p] = 0.f;

#pragma unroll
    for (int ks = 0; ks < 2; ks++) {
        unsigned ah[2][4], al[2][4];
#pragma unroll
        for (int mt = 0; mt < 2; mt++) {
            int off = (wm + mt * 16 + rowoff) * SROW + ks * 16 + coloff;
            ldx4(ah[mt], (unsigned)__cvta_generic_to_shared(&Ah[off]));
            ldx4(al[mt], (unsigned)__cvta_generic_to_shared(&Al[off]));
        }
#pragma unroll
        for (int nt = 0; nt < 4; nt++) {
            int off = (wn + nt * 16 + rowoff) * SROW + ks * 16 + coloff;
            unsigned bh[4], bl[4];
            ldx4(bh, (unsigned)__cvta_generic_to_shared(&Bh[off]));
            ldx4(bl, (unsigned)__cvta_generic_to_shared(&Bl[off]));
#pragma unroll
            for (int mt = 0; mt < 2; mt++) {
                mma16816(acc[mt][2 * nt],     ah[mt], bh[0], bh[2]);
                mma16816(acc[mt][2 * nt],     ah[mt], bl[0], bl[2]);
                mma16816(acc[mt][2 * nt],     al[mt], bh[0], bh[2]);
                mma16816(acc[mt][2 * nt + 1], ah[mt], bh[1], bh[3]);
                mma16816(acc[mt][2 * nt + 1], ah[mt], bl[1], bl[3]);
                mma16816(acc[mt][2 * nt + 1], al[mt], bh[1], bh[3]);
            }
        }
    }

    int g  = lane >> 2;
    int tg = lane & 3;
#pragma unroll
    for (int mt = 0; mt < 2; mt++) {
        int row0 = bi * 128 + wm + mt * 16 + g;
#pragma unroll
        for (int n = 0; n < 8; n++) {
            int col = bj * 128 + wn + n * 8 + tg * 2;
            float2* p0 = (float2*)(C + (size_t)row0 * NN + col);
            float2* p1 = (float2*)(C + (size_t)(row0 + 8) * NN + col);
            *p0 = make_float2(acc[mt][n][0], acc[mt][n][1]);
            *p1 = make_float2(acc[mt][n][2], acc[mt][n][3]);
        }
    }
}

// ---------------------------------------------------------------------------
extern "C" void kernel_launch(void* const* d_in, const int* in_sizes, int n_in,
                              void* d_out, int out_size) {
    const unsigned* xbuf  = (const unsigned*)d_in[0];
    const unsigned* eibuf = (const unsigned*)d_in[1];
    const float*    ea    = (const float*)d_in[2];
    const float*    emb   = (const float*)d_in[3];
    const float*    W1    = (const float*)d_in[4];
    const float*    b1    = (const float*)d_in[5];
    const float*    E1w   = (const float*)d_in[6];
    const float*    E1b   = (const float*)d_in[7];
    const float*    W2    = (const float*)d_in[8];
    const float*    b2    = (const float*)d_in[9];
    const float*    E2w   = (const float*)d_in[10];
    const float*    E2b   = (const float*)d_in[11];
    float* out = (float*)d_out;

    k_convert<<<(NE + 255) / 256, 256>>>(xbuf, eibuf);      // idx 0
    k_embed<<<NN * 32 / 256, 256>>>((const float4*)emb);    // idx 1
    k_prepw<<<8, 256>>>(E1w);                               // idx 2
    k_edge1<<<NE / ET, 256>>>((const float4*)ea,            // idx 3 (profiled)
                              (const float4*)E1b);
    k_prepw1<<<32, 256>>>(W1);
    k_lin1<<<NN / 64, 256>>>(b1);
    k_prepw2<<<4, 256>>>(E2w);
    k_edge2<<<NE / ET, 256>>>((const float4*)ea,
                              (const float2*)E2b);
    k_lin2<<<NN / 8, 256>>>(W2, b2);
    dim3 g(NN / 128, NN / 128);
    k_gemm<<<g, 256>>>(out);
}

// round 12
// speedup vs baseline: 2.0801x; 1.2004x over previous
#include <cuda_runtime.h>
#include <cuda_bf16.h>

// GINE-conv network:
//   h = emb[x]; h = leaky_relu(gine(h, E1)); h2 = gine(h, E2); out = h2 @ h2.T
// N=8192, E=262144, dims 128 -> 64 -> 32, out 8192x8192 f32.
// R12 vs R11 (190.5us):
//   (1) k_edge1: 32-edge tiles (smem 46->27KB, 4->6 blocks/SM) for occupancy;
//   (2) k_gemm: symmetric — compute bj>=bi tiles only, mirror-write transpose.

#define NN     8192
#define NE     262144
#define EMB    128
#define D1     64
#define D2     32
#define EPSF   1e-9f
#define SLOPEF 0.01f

__device__ __align__(16) float g_h[NN * EMB];
__device__ __align__(16) float g_agg1[NN * EMB];
__device__ __align__(16) float g_h1[NN * D1];
__device__ __align__(16) float g_agg2[NN * D1];
__device__ __align__(16) unsigned short g_h2hi[NN * D2];   // bf16 hi
__device__ __align__(16) unsigned short g_h2lo[NN * D2];   // bf16 lo residual
__device__ __align__(16) unsigned short g_w1hi[EMB * 16];  // E1w^T hi [n][k]
__device__ __align__(16) unsigned short g_w1lo[EMB * 16];  // E1w^T lo [n][k]
__device__ __align__(16) unsigned short g_w2hi[D1 * 16];   // E2w^T hi [n][k]
__device__ __align__(16) unsigned short g_w2lo[D1 * 16];   // E2w^T lo [n][k]
__device__ __align__(16) unsigned short g_w1bh[D1 * EMB];  // W1^T hi [n][k]
__device__ __align__(16) unsigned short g_w1bl[D1 * EMB];  // W1^T lo [n][k]
__device__ int g_x[NN];
__device__ int g_src[NE];
__device__ int g_dst[NE];

__device__ __forceinline__ void ldx4(unsigned r[4], unsigned addr) {
    asm volatile("ldmatrix.sync.aligned.m8n8.x4.shared.b16 {%0,%1,%2,%3}, [%4];"
                 : "=r"(r[0]), "=r"(r[1]), "=r"(r[2]), "=r"(r[3]) : "r"(addr));
}
__device__ __forceinline__ void mma16816(float c[4], const unsigned a[4],
                                         unsigned b0, unsigned b1) {
    asm volatile(
        "mma.sync.aligned.m16n8k16.row.col.f32.bf16.bf16.f32 "
        "{%0,%1,%2,%3}, {%4,%5,%6,%7}, {%8,%9}, {%0,%1,%2,%3};"
        : "+f"(c[0]), "+f"(c[1]), "+f"(c[2]), "+f"(c[3])
        : "r"(a[0]), "r"(a[1]), "r"(a[2]), "r"(a[3]), "r"(b0), "r"(b1));
}
__device__ __forceinline__ void bf16split(float v, unsigned short& h,
                                          unsigned short& l) {
    __nv_bfloat16 hi = __float2bfloat16_rn(v);
    float res = v - __bfloat162float(hi);
    __nv_bfloat16 lo = __float2bfloat16_rn(res);
    h = *(unsigned short*)&hi;
    l = *(unsigned short*)&lo;
}

// ---------------------------------------------------------------------------
// K0: normalize index dtypes (int64 vs int32 delivery; detection as before).
// ---------------------------------------------------------------------------
__global__ void k_convert(const unsigned* __restrict__ xbuf,
                          const unsigned* __restrict__ eibuf) {
    unsigned odd_or = 0;
#pragma unroll
    for (int i = 0; i < 32; i++) odd_or |= eibuf[2 * i + 1];
    bool mode64 = (odd_or == 0);

    int t = blockIdx.x * blockDim.x + threadIdx.x;
    if (t < NE) {
        g_src[t] = (int)(mode64 ? eibuf[2 * t]        : eibuf[t]);
        g_dst[t] = (int)(mode64 ? eibuf[2 * (NE + t)] : eibuf[NE + t]);
    }
    if (t < NN) g_x[t] = (int)(mode64 ? xbuf[2 * t] : xbuf[t]);
}

// ---------------------------------------------------------------------------
// K1: h = emb[x];  agg1 = (1+eps)*h
// ---------------------------------------------------------------------------
__global__ void k_embed(const float4* __restrict__ emb4) {
    int t = blockIdx.x * blockDim.x + threadIdx.x;
    int node = t >> 5;
    int c    = t & 31;
    float4 v = emb4[g_x[node] * 32 + c];
    ((float4*)g_h)[t] = v;
    float4 a = make_float4(v.x * (1.f + EPSF), v.y * (1.f + EPSF),
                           v.z * (1.f + EPSF), v.w * (1.f + EPSF));
    ((float4*)g_agg1)[t] = a;
}

// ---------------------------------------------------------------------------
// Weight prep kernels (bf16 hi/lo transposed splits).
// ---------------------------------------------------------------------------
__global__ void k_prepw(const float* __restrict__ E1w) {
    int t = blockIdx.x * blockDim.x + threadIdx.x;   // 0..2047
    int n = t >> 4;
    int k = t & 15;
    unsigned short h, l;
    bf16split(E1w[k * EMB + n], h, l);
    g_w1hi[t] = h;
    g_w1lo[t] = l;
}

__global__ void k_prepw2(const float* __restrict__ E2w) {
    int t = blockIdx.x * blockDim.x + threadIdx.x;   // 0..1023
    int n = t >> 4;
    int k = t & 15;
    unsigned short h, l;
    bf16split(E2w[k * D1 + n], h, l);
    g_w2hi[t] = h;
    g_w2lo[t] = l;
}

// W1 [128 k][64 n] -> W1^T hi/lo [64 n][128 k]
__global__ void k_prepw1(const float* __restrict__ W1) {
    int t = blockIdx.x * blockDim.x + threadIdx.x;   // 0..8191
    int n = t >> 7;
    int kk = t & 127;
    unsigned short h, l;
    bf16split(W1[kk * D1 + n], h, l);
    g_w1bh[t] = h;
    g_w1bl[t] = l;
}

// ---------------------------------------------------------------------------
// K2: edge pass 1. Block = 32-edge tile (smaller smem -> higher occupancy).
// Phase A: ee[32][128] = ea_tile @ E1w via bf16 hi/lo mma -> smem.
//   8 warps: w>>2 -> m16 group (2), w&3 -> 32-col quarter of 128.
// Phase B: warp per edge (4 iter): m = relu(h[src]+ee+b); red.v4 agg1[dst].
// ---------------------------------------------------------------------------
#define ET1  32
#define EESTRIDE 132

__global__ void __launch_bounds__(256, 6)
k_edge1(const float4* __restrict__ ea4,
        const float4* __restrict__ b4) {   // E1b as 32 float4
    __shared__ __align__(16) unsigned short sEaH[ET1][16];
    __shared__ __align__(16) unsigned short sEaL[ET1][16];
    __shared__ __align__(16) unsigned short sWtH[EMB][16];
    __shared__ __align__(16) unsigned short sWtL[EMB][16];
    __shared__ __align__(16) float sEe[ET1][EESTRIDE];

    int tid  = threadIdx.x;
    int lane = tid & 31;
    int w    = tid >> 5;
    int e0   = blockIdx.x * ET1;

    float4 bias = b4[lane];

    {
        const unsigned* wh = (const unsigned*)g_w1hi;
        const unsigned* wl = (const unsigned*)g_w1lo;
        unsigned* dh = (unsigned*)sWtH;
        unsigned* dl = (unsigned*)sWtL;
        for (int i = tid; i < EMB * 8; i += 256) { dh[i] = wh[i]; dl[i] = wl[i]; }
    }
    if (tid < ET1 * 4) {
        int el = tid >> 2;
        int pt = tid & 3;
        float4 v = ea4[(size_t)(e0 + el) * 4 + pt];
        unsigned short h_[4], l_[4];
        float vv[4] = {v.x, v.y, v.z, v.w};
#pragma unroll
        for (int i = 0; i < 4; i++) bf16split(vv[i], h_[i], l_[i]);
        *(uint2*)&sEaH[el][pt * 4] = *(uint2*)h_;
        *(uint2*)&sEaL[el][pt * 4] = *(uint2*)l_;
    }
    __syncthreads();

    // Phase A: warp (w>>2 -> m16 group of 2, w&3 -> 32-col quarter)
    {
        int wm = (w >> 2) * 16;
        int wn = (w & 3) * 32;
        int q  = lane >> 3;
        int li = lane & 7;
        int rowoff = (q & 1) * 8 + li;
        int coloff = (q >> 1) * 8;

        unsigned ah[4], al[4];
        ldx4(ah, (unsigned)__cvta_generic_to_shared(&sEaH[wm + rowoff][coloff]));
        ldx4(al, (unsigned)__cvta_generic_to_shared(&sEaL[wm + rowoff][coloff]));

        float acc[4][4];
#pragma unroll
        for (int n = 0; n < 4; n++)
#pragma unroll
            for (int p = 0; p < 4; p++) acc[n][p] = 0.f;

#pragma unroll
        for (int nt = 0; nt < 2; nt++) {
            unsigned bh[4], bl[4];
            ldx4(bh, (unsigned)__cvta_generic_to_shared(&sWtH[wn + nt * 16 + rowoff][coloff]));
            ldx4(bl, (unsigned)__cvta_generic_to_shared(&sWtL[wn + nt * 16 + rowoff][coloff]));
            mma16816(acc[2 * nt],     ah, bh[0], bh[2]);
            mma16816(acc[2 * nt],     ah, bl[0], bl[2]);
            mma16816(acc[2 * nt],     al, bh[0], bh[2]);
            mma16816(acc[2 * nt + 1], ah, bh[1], bh[3]);
            mma16816(acc[2 * nt + 1], ah, bl[1], bl[3]);
            mma16816(acc[2 * nt + 1], al, bh[1], bh[3]);
        }

        int g  = lane >> 2;
        int tg = lane & 3;
#pragma unroll
        for (int n = 0; n < 4; n++) {
            int col = wn + n * 8 + tg * 2;
            *(float2*)&sEe[wm + g][col]     = make_float2(acc[n][0], acc[n][1]);
            *(float2*)&sEe[wm + g + 8][col] = make_float2(acc[n][2], acc[n][3]);
        }
    }
    __syncthreads();

    // Phase B: warp per edge (8 warps x 4 iterations).
    const float4* h4 = (const float4*)g_h;
#pragma unroll
    for (int it = 0; it < ET1 / 8; it++) {
        int el = w * (ET1 / 8) + it;
        int e  = e0 + el;
        int src = g_src[e];
        int dst = g_dst[e];

        float4 ev = *(const float4*)&sEe[el][lane * 4];
        float4 hv = h4[src * 32 + lane];
        float m0 = fmaxf(hv.x + ev.x + bias.x, 0.f);
        float m1 = fmaxf(hv.y + ev.y + bias.y, 0.f);
        float m2 = fmaxf(hv.z + ev.z + bias.z, 0.f);
        float m3 = fmaxf(hv.w + ev.w + bias.w, 0.f);

        float* p = g_agg1 + (size_t)dst * EMB + lane * 4;
        asm volatile("red.global.add.v4.f32 [%0], {%1,%2,%3,%4};"
                     :: "l"(p), "f"(m0), "f"(m1), "f"(m2), "f"(m3)
                     : "memory");
    }
}

// ---------------------------------------------------------------------------
// K3: h1 = leaky_relu(agg1 @ W1 + b1); agg2 = (1+eps)*h1.  TENSORIZED
// (R11-validated). Block = 64 nodes, 8 warps (4m x 2n), K=128 in two halves.
// ---------------------------------------------------------------------------
#define L1S 72

__global__ void __launch_bounds__(256)
k_lin1(const float* __restrict__ b1) {
    __shared__ __align__(16) unsigned short sAh[64][L1S];
    __shared__ __align__(16) unsigned short sAl[64][L1S];
    __shared__ __align__(16) unsigned short sBh[64][L1S];
    __shared__ __align__(16) unsigned short sBl[64][L1S];

    int tid  = threadIdx.x;
    int lane = tid & 31;
    int w    = tid >> 5;
    int node0 = blockIdx.x * 64;

    int wm = (w >> 1) * 16;
    int wn = (w & 1) * 32;
    int q  = lane >> 3;
    int li = lane & 7;
    int rowoff = (q & 1) * 8 + li;
    int coloff = (q >> 1) * 8;
    int g  = lane >> 2;
    int tg = lane & 3;

    float acc[4][4];
#pragma unroll
    for (int n = 0; n < 4; n++) {
        int col = wn + n * 8 + tg * 2;
        float bb0 = b1[col];
        float bb1 = b1[col + 1];
        acc[n][0] = bb0; acc[n][1] = bb1;
        acc[n][2] = bb0; acc[n][3] = bb1;
    }

    const unsigned* wb_h = (const unsigned*)g_w1bh;   // [64 n][64 u32]
    const unsigned* wb_l = (const unsigned*)g_w1bl;

#pragma unroll
    for (int kh = 0; kh < 2; kh++) {
        if (kh) __syncthreads();
#pragma unroll
        for (int i = 0; i < 4; i++) {
            int lin = tid + i * 256;
            int nd  = lin >> 4;
            int c4  = lin & 15;
            float4 v = *(const float4*)&g_agg1[(size_t)(node0 + nd) * EMB + kh * 64 + c4 * 4];
            unsigned short h_[4], l_[4];
            float vv[4] = {v.x, v.y, v.z, v.w};
#pragma unroll
            for (int j = 0; j < 4; j++) bf16split(vv[j], h_[j], l_[j]);
            *(uint2*)&sAh[nd][c4 * 4] = *(uint2*)h_;
            *(uint2*)&sAl[nd][c4 * 4] = *(uint2*)l_;
        }
#pragma unroll
        for (int i = 0; i < 8; i++) {
            int lin = tid + i * 256;          // 0..2047
            int n   = lin >> 5;
            int c2  = lin & 31;
            ((unsigned*)&sBh[n][c2 * 2])[0] = wb_h[n * 64 + kh * 32 + c2];
            ((unsigned*)&sBl[n][c2 * 2])[0] = wb_l[n * 64 + kh * 32 + c2];
        }
        __syncthreads();

#pragma unroll
        for (int ks = 0; ks < 4; ks++) {
            unsigned ah[4], al[4];
            ldx4(ah, (unsigned)__cvta_generic_to_shared(&sAh[wm + rowoff][ks * 16 + coloff]));
            ldx4(al, (unsigned)__cvta_generic_to_shared(&sAl[wm + rowoff][ks * 16 + coloff]));
#pragma unroll
            for (int nt = 0; nt < 2; nt++) {
                unsigned bh[4], bl[4];
                ldx4(bh, (unsigned)__cvta_generic_to_shared(&sBh[wn + nt * 16 + rowoff][ks * 16 + coloff]));
                ldx4(bl, (unsigned)__cvta_generic_to_shared(&sBl[wn + nt * 16 + rowoff][ks * 16 + coloff]));
                mma16816(acc[2 * nt],     ah, bh[0], bh[2]);
                mma16816(acc[2 * nt],     ah, bl[0], bl[2]);
                mma16816(acc[2 * nt],     al, bh[0], bh[2]);
                mma16816(acc[2 * nt + 1], ah, bh[1], bh[3]);
                mma16816(acc[2 * nt + 1], ah, bl[1], bl[3]);
                mma16816(acc[2 * nt + 1], al, bh[1], bh[3]);
            }
        }
    }

#pragma unroll
    for (int n = 0; n < 4; n++) {
        int col = wn + n * 8 + tg * 2;
        float v0 = acc[n][0], v1 = acc[n][1], v2 = acc[n][2], v3 = acc[n][3];
        float a0 = v0 >= 0.f ? v0 : SLOPEF * v0;
        float a1 = v1 >= 0.f ? v1 : SLOPEF * v1;
        float a2 = v2 >= 0.f ? v2 : SLOPEF * v2;
        float a3 = v3 >= 0.f ? v3 : SLOPEF * v3;
        size_t r0 = (size_t)(node0 + wm + g) * D1 + col;
        size_t r1 = (size_t)(node0 + wm + g + 8) * D1 + col;
        *(float2*)&g_h1[r0]   = make_float2(a0, a1);
        *(float2*)&g_h1[r1]   = make_float2(a2, a3);
        *(float2*)&g_agg2[r0] = make_float2((1.f + EPSF) * a0, (1.f + EPSF) * a1);
        *(float2*)&g_agg2[r1] = make_float2((1.f + EPSF) * a2, (1.f + EPSF) * a3);
    }
}

// ---------------------------------------------------------------------------
// K4: edge pass 2, tensorized (R8-validated). Block = 64-edge tile.
// ---------------------------------------------------------------------------
#define ET   64
#define EESTRIDE2 68

__global__ void __launch_bounds__(256)
k_edge2(const float4* __restrict__ ea4,
        const float2* __restrict__ b2v) {  // E2b as 32 float2
    __shared__ __align__(16) unsigned short sEaH[ET][16];
    __shared__ __align__(16) unsigned short sEaL[ET][16];
    __shared__ __align__(16) unsigned short sW2H[D1][16];
    __shared__ __align__(16) unsigned short sW2L[D1][16];
    __shared__ __align__(16) float sEe[ET][EESTRIDE2];

    int tid  = threadIdx.x;
    int lane = tid & 31;
    int w    = tid >> 5;
    int e0   = blockIdx.x * ET;

    float2 bias = b2v[lane];

    {
        const unsigned* wh = (const unsigned*)g_w2hi;
        const unsigned* wl = (const unsigned*)g_w2lo;
        unsigned* dh = (unsigned*)sW2H;
        unsigned* dl = (unsigned*)sW2L;
        for (int i = tid; i < D1 * 8; i += 256) { dh[i] = wh[i]; dl[i] = wl[i]; }
    }
    {
        int el = tid >> 2;
        int pt = tid & 3;
        float4 v = ea4[(size_t)(e0 + el) * 4 + pt];
        unsigned short h_[4], l_[4];
        float vv[4] = {v.x, v.y, v.z, v.w};
#pragma unroll
        for (int i = 0; i < 4; i++) bf16split(vv[i], h_[i], l_[i]);
        *(uint2*)&sEaH[el][pt * 4] = *(uint2*)h_;
        *(uint2*)&sEaL[el][pt * 4] = *(uint2*)l_;
    }
    __syncthreads();

    {
        int wm = (w >> 1) * 16;
        int wn = (w & 1) * 32;
        int q  = lane >> 3;
        int li = lane & 7;
        int rowoff = (q & 1) * 8 + li;
        int coloff = (q >> 1) * 8;

        unsigned ah[4], al[4];
        ldx4(ah, (unsigned)__cvta_generic_to_shared(&sEaH[wm + rowoff][coloff]));
        ldx4(al, (unsigned)__cvta_generic_to_shared(&sEaL[wm + rowoff][coloff]));

        float acc[4][4];
#pragma unroll
        for (int n = 0; n < 4; n++)
#pragma unroll
            for (int p = 0; p < 4; p++) acc[n][p] = 0.f;

#pragma unroll
        for (int nt = 0; nt < 2; nt++) {
            unsigned bh[4], bl[4];
            ldx4(bh, (unsigned)__cvta_generic_to_shared(&sW2H[wn + nt * 16 + rowoff][coloff]));
            ldx4(bl, (unsigned)__cvta_generic_to_shared(&sW2L[wn + nt * 16 + rowoff][coloff]));
            mma16816(acc[2 * nt],     ah, bh[0], bh[2]);
            mma16816(acc[2 * nt],     ah, bl[0], bl[2]);
            mma16816(acc[2 * nt],     al, bh[0], bh[2]);
            mma16816(acc[2 * nt + 1], ah, bh[1], bh[3]);
            mma16816(acc[2 * nt + 1], ah, bl[1], bl[3]);
            mma16816(acc[2 * nt + 1], al, bh[1], bh[3]);
        }

        int g  = lane >> 2;
        int tg = lane & 3;
#pragma unroll
        for (int n = 0; n < 4; n++) {
            int col = wn + n * 8 + tg * 2;
            *(float2*)&sEe[wm + g][col]     = make_float2(acc[n][0], acc[n][1]);
            *(float2*)&sEe[wm + g + 8][col] = make_float2(acc[n][2], acc[n][3]);
        }
    }
    __syncthreads();

    const float2* h2v = (const float2*)g_h1;
#pragma unroll
    for (int it = 0; it < ET / 8; it++) {
        int el = w * (ET / 8) + it;
        int e  = e0 + el;
        int src = g_src[e];
        int dst = g_dst[e];

        float2 ev = *(const float2*)&sEe[el][lane * 2];
        float2 hv = h2v[src * 32 + lane];
        float m0 = fmaxf(hv.x + ev.x + bias.x, 0.f);
        float m1 = fmaxf(hv.y + ev.y + bias.y, 0.f);

        float* p = g_agg2 + (size_t)dst * D1 + lane * 2;
        asm volatile("red.global.add.v2.f32 [%0], {%1,%2};"
                     :: "l"(p), "f"(m0), "f"(m1)
                     : "memory");
    }
}

// ---------------------------------------------------------------------------
// K5: h2 = agg2 @ W2 + b2, stored as bf16 hi + bf16 lo residual.
// ---------------------------------------------------------------------------
__global__ void __launch_bounds__(256)
k_lin2(const float* __restrict__ W2, const float* __restrict__ b2) {
    __shared__ float sW[D1][D2 + 1];
    __shared__ float srow[8][D1 + 4];

    int tid  = threadIdx.x;
    int warp = tid >> 5;
    int lane = tid & 31;

    for (int i = tid; i < D1 * D2; i += 256)
        sW[i >> 5][i & 31] = W2[i];

    int n = blockIdx.x * 8 + warp;
    float2 rv = *(const float2*)(g_agg2 + (size_t)n * D1 + lane * 2);
    srow[warp][lane * 2]     = rv.x;
    srow[warp][lane * 2 + 1] = rv.y;
    __syncthreads();

    float acc = b2[lane];
#pragma unroll
    for (int k = 0; k < D1; k++)
        acc = fmaf(srow[warp][k], sW[k][lane], acc);

    unsigned short h, l;
    bf16split(acc, h, l);
    g_h2hi[(size_t)n * D2 + lane] = h;
    g_h2lo[(size_t)n * D2 + lane] = l;
}

// ---------------------------------------------------------------------------
// K6: C = h2 @ h2^T via bf16 tensor cores, uint4 staging. SYMMETRIC:
// compute bj >= bi tiles only; off-diagonal tiles also write the transpose.
// ---------------------------------------------------------------------------
#define SROW 40

__global__ void __launch_bounds__(256)
k_gemm(float* __restrict__ C) {
    int bi = blockIdx.y;
    int bj = blockIdx.x;
    if (bj < bi) return;

    __shared__ __align__(16) unsigned short Ah[128 * SROW];
    __shared__ __align__(16) unsigned short Al[128 * SROW];
    __shared__ __align__(16) unsigned short Bh[128 * SROW];
    __shared__ __align__(16) unsigned short Bl[128 * SROW];

    int tid = threadIdx.x;

    {
        const uint4* h2h4 = (const uint4*)g_h2hi;
        const uint4* h2l4 = (const uint4*)g_h2lo;
        uint4* Ah4 = (uint4*)Ah;
        uint4* Al4 = (uint4*)Al;
        uint4* Bh4 = (uint4*)Bh;
        uint4* Bl4 = (uint4*)Bl;
#pragma unroll
        for (int i = 0; i < 2; i++) {
            int idx = tid + i * 256;       // 0..511
            int r = idx >> 2;
            int q = idx & 3;
            int sm = r * 5 + q;
            Ah4[sm] = h2h4[(size_t)(bi * 128 + r) * 4 + q];
            Al4[sm] = h2l4[(size_t)(bi * 128 + r) * 4 + q];
            Bh4[sm] = h2h4[(size_t)(bj * 128 + r) * 4 + q];
            Bl4[sm] = h2l4[(size_t)(bj * 128 + r) * 4 + q];
        }
    }
    __syncthreads();

    int w    = tid >> 5;
    int lane = tid & 31;
    int wm   = (w >> 1) * 32;
    int wn   = (w & 1) * 64;
    int q    = lane >> 3;
    int li   = lane & 7;
    int rowoff = (q & 1) * 8 + li;
    int coloff = (q >> 1) * 8;

    float acc[2][8][4];
#pragma unroll
    for (int mt = 0; mt < 2; mt++)
#pragma unroll
        for (int n = 0; n < 8; n++)
#pragma unroll
            for (int p = 0; p < 4; p++) acc[mt][n][p] = 0.f;

#pragma unroll
    for (int ks = 0; ks < 2; ks++) {
        unsigned ah[2][4], al[2][4];
#pragma unroll
        for (int mt = 0; mt < 2; mt++) {
            int off = (wm + mt * 16 + rowoff) * SROW + ks * 16 + coloff;
            ldx4(ah[mt], (unsigned)__cvta_generic_to_shared(&Ah[off]));
            ldx4(al[mt], (unsigned)__cvta_generic_to_shared(&Al[off]));
        }
#pragma unroll
        for (int nt = 0; nt < 4; nt++) {
            int off = (wn + nt * 16 + rowoff) * SROW + ks * 16 + coloff;
            unsigned bh[4], bl[4];
            ldx4(bh, (unsigned)__cvta_generic_to_shared(&Bh[off]));
            ldx4(bl, (unsigned)__cvta_generic_to_shared(&Bl[off]));
#pragma unroll
            for (int mt = 0; mt < 2; mt++) {
                mma16816(acc[mt][2 * nt],     ah[mt], bh[0], bh[2]);
                mma16816(acc[mt][2 * nt],     ah[mt], bl[0], bl[2]);
                mma16816(acc[mt][2 * nt],     al[mt], bh[0], bh[2]);
                mma16816(acc[mt][2 * nt + 1], ah[mt], bh[1], bh[3]);
                mma16816(acc[mt][2 * nt + 1], ah[mt], bl[1], bl[3]);
                mma16816(acc[mt][2 * nt + 1], al[mt], bh[1], bh[3]);
            }
        }
    }

    int g  = lane >> 2;
    int tg = lane & 3;
#pragma unroll
    for (int mt = 0; mt < 2; mt++) {
        int row0 = bi * 128 + wm + mt * 16 + g;
#pragma unroll
        for (int n = 0; n < 8; n++) {
            int col = bj * 128 + wn + n * 8 + tg * 2;
            float2* p0 = (float2*)(C + (size_t)row0 * NN + col);
            float2* p1 = (float2*)(C + (size_t)(row0 + 8) * NN + col);
            *p0 = make_float2(acc[mt][n][0], acc[mt][n][1]);
            *p1 = make_float2(acc[mt][n][2], acc[mt][n][3]);
        }
    }
    if (bi != bj) {
        // Mirror: C[col][row] = C[row][col]. For fixed tg, 8 consecutive g
        // lanes write 8 consecutive rows -> 32B contiguous per STG.32 group.
#pragma unroll
        for (int mt = 0; mt < 2; mt++) {
            int row0 = bi * 128 + wm + mt * 16 + g;
#pragma unroll
            for (int n = 0; n < 8; n++) {
                int col = bj * 128 + wn + n * 8 + tg * 2;
                C[(size_t)col * NN + row0]           = acc[mt][n][0];
                C[(size_t)(col + 1) * NN + row0]     = acc[mt][n][1];
                C[(size_t)col * NN + row0 + 8]       = acc[mt][n][2];
                C[(size_t)(col + 1) * NN + row0 + 8] = acc[mt][n][3];
            }
        }
    }
}

// ---------------------------------------------------------------------------
extern "C" void kernel_launch(void* const* d_in, const int* in_sizes, int n_in,
                              void* d_out, int out_size) {
    const unsigned* xbuf  = (const unsigned*)d_in[0];
    const unsigned* eibuf = (const unsigned*)d_in[1];
    const float*    ea    = (const float*)d_in[2];
    const float*    emb   = (const float*)d_in[3];
    const float*    W1    = (const float*)d_in[4];
    const float*    b1    = (const float*)d_in[5];
    const float*    E1w   = (const float*)d_in[6];
    const float*    E1b   = (const float*)d_in[7];
    const float*    W2    = (const float*)d_in[8];
    const float*    b2    = (const float*)d_in[9];
    const float*    E2w   = (const float*)d_in[10];
    const float*    E2b   = (const float*)d_in[11];
    float* out = (float*)d_out;

    k_convert<<<(NE + 255) / 256, 256>>>(xbuf, eibuf);      // idx 0
    k_embed<<<NN * 32 / 256, 256>>>((const float4*)emb);    // idx 1
    k_prepw<<<8, 256>>>(E1w);                               // idx 2
    k_edge1<<<NE / ET1, 256>>>((const float4*)ea,           // idx 3 (profiled)
                               (const float4*)E1b);
    k_prepw1<<<32, 256>>>(W1);
    k_lin1<<<NN / 64, 256>>>(b1);
    k_prepw2<<<4, 256>>>(E2w);
    k_edge2<<<NE / ET, 256>>>((const float4*)ea,
                              (const float2*)E2b);
    k_lin2<<<NN / 8, 256>>>(W2, b2);
    dim3 g(NN / 128, NN / 128);
    k_gemm<<<g, 256>>>(out);
}